// round 1
// baseline (speedup 1.0000x reference)
#include <cuda_runtime.h>
#include <cuda_bf16.h>
#include <math.h>

// Problem constants
#define B_  2
#define L_  2048
#define NT  4096            // B*L tokens
#define D_  1024
#define H_  16
#define DH  64
#define D3  3072
#define EPS 1e-5f

// ---------------- scratch (device globals; no allocation) ----------------
__device__ float g_h[NT * D_];        // LN1 output            [NT, D]
__device__ float g_qkv[NT * D3];      // QKV gemm output       [NT, 3D]
__device__ float g_qT[NT * D_];       // [B,H,L,DH]
__device__ float g_kT[NT * D_];       // [B,H,L,DH]
__device__ float g_vT[NT * D_];       // [B,H,L,DH]
__device__ float g_ctx[NT * D_];      // [B,L,H,DH] == [NT, D]
__device__ float g_cos[L_ * 32];
__device__ float g_sin[L_ * 32];

// ---------------- RoPE table ----------------
__global__ void rope_table_kernel() {
    int idx = blockIdx.x * blockDim.x + threadIdx.x;   // 0 .. 2048*32-1
    if (idx >= L_ * 32) return;
    int l = idx >> 5;
    int j = idx & 31;
    float inv = powf(10000.0f, -(float)j / 32.0f);
    float ang = (float)l * inv;
    float s, c;
    sincosf(ang, &s, &c);
    g_cos[idx] = c;
    g_sin[idx] = s;
}

// ---------------- LN1: y = (x-mu)*rstd*w + b ----------------
__global__ void ln1_kernel(const float* __restrict__ x,
                           const float* __restrict__ w,
                           const float* __restrict__ b) {
    int n = blockIdx.x;
    const float* xr = x + (size_t)n * D_;
    int t = threadIdx.x;                      // 256 threads, 4 elems each
    float4 v = *(const float4*)&xr[t * 4];
    float s  = v.x + v.y + v.z + v.w;
    float s2 = v.x*v.x + v.y*v.y + v.z*v.z + v.w*v.w;
    #pragma unroll
    for (int o = 16; o >= 1; o >>= 1) {
        s  += __shfl_xor_sync(0xffffffffu, s,  o);
        s2 += __shfl_xor_sync(0xffffffffu, s2, o);
    }
    __shared__ float red[2][8];
    int lane = t & 31, wp = t >> 5;
    if (lane == 0) { red[0][wp] = s; red[1][wp] = s2; }
    __syncthreads();
    __shared__ float stat[2];
    if (t == 0) {
        float a = 0.f, c = 0.f;
        #pragma unroll
        for (int i = 0; i < 8; i++) { a += red[0][i]; c += red[1][i]; }
        float mu  = a * (1.0f / D_);
        float var = c * (1.0f / D_) - mu * mu;
        stat[0] = mu;
        stat[1] = rsqrtf(var + EPS);
    }
    __syncthreads();
    float mu = stat[0], rs = stat[1];
    float4 wv = *(const float4*)&w[t * 4];
    float4 bv = *(const float4*)&b[t * 4];
    float4 o;
    o.x = (v.x - mu) * rs * wv.x + bv.x;
    o.y = (v.y - mu) * rs * wv.y + bv.y;
    o.z = (v.z - mu) * rs * wv.z + bv.z;
    o.w = (v.w - mu) * rs * wv.w + bv.w;
    *(float4*)&g_h[(size_t)n * D_ + t * 4] = o;
}

// ---------------- generic SGEMM: C[M,N] = A[M,K] * B[N,K]^T ----------------
// BM=BN=128, BK=8, 256 threads, 8x8 per thread.
__global__ __launch_bounds__(256) void sgemm_nt(const float* __restrict__ A,
                                                const float* __restrict__ Bm,
                                                float* __restrict__ C,
                                                int M, int N, int K) {
    __shared__ float As[8][128];
    __shared__ float Bs[8][128];
    int tid = threadIdx.x;
    int tx = tid & 15, ty = tid >> 4;
    int row0 = blockIdx.y * 128, col0 = blockIdx.x * 128;
    int lr = tid >> 1;            // 0..127
    int lc = (tid & 1) * 4;       // 0 or 4

    const float* Ag = A  + (size_t)(row0 + lr) * K + lc;
    const float* Bg = Bm + (size_t)(col0 + lr) * K + lc;

    float acc[8][8];
    #pragma unroll
    for (int i = 0; i < 8; i++)
        #pragma unroll
        for (int j = 0; j < 8; j++) acc[i][j] = 0.f;

    for (int k0 = 0; k0 < K; k0 += 8) {
        float4 a = *(const float4*)(Ag + k0);
        float4 b = *(const float4*)(Bg + k0);
        As[lc+0][lr] = a.x; As[lc+1][lr] = a.y; As[lc+2][lr] = a.z; As[lc+3][lr] = a.w;
        Bs[lc+0][lr] = b.x; Bs[lc+1][lr] = b.y; Bs[lc+2][lr] = b.z; Bs[lc+3][lr] = b.w;
        __syncthreads();
        #pragma unroll
        for (int kk = 0; kk < 8; kk++) {
            float4 a0 = *(const float4*)&As[kk][ty * 8];
            float4 a1 = *(const float4*)&As[kk][ty * 8 + 4];
            float4 b0 = *(const float4*)&Bs[kk][tx * 8];
            float4 b1 = *(const float4*)&Bs[kk][tx * 8 + 4];
            float am[8] = {a0.x,a0.y,a0.z,a0.w,a1.x,a1.y,a1.z,a1.w};
            float bn[8] = {b0.x,b0.y,b0.z,b0.w,b1.x,b1.y,b1.z,b1.w};
            #pragma unroll
            for (int i = 0; i < 8; i++)
                #pragma unroll
                for (int j = 0; j < 8; j++)
                    acc[i][j] = fmaf(am[i], bn[j], acc[i][j]);
        }
        __syncthreads();
    }
    #pragma unroll
    for (int i = 0; i < 8; i++) {
        size_t r = (size_t)(row0 + ty * 8 + i) * N + col0 + tx * 8;
        *(float4*)&C[r]     = make_float4(acc[i][0], acc[i][1], acc[i][2], acc[i][3]);
        *(float4*)&C[r + 4] = make_float4(acc[i][4], acc[i][5], acc[i][6], acc[i][7]);
    }
}

// ---------------- fused QK-LN + RoPE + transpose + V copy ----------------
__global__ void qk_rope_kernel(const float* __restrict__ qw,
                               const float* __restrict__ kw) {
    int n = blockIdx.x;
    int b = n >> 11;           // / 2048
    int l = n & 2047;
    const float* q = g_qkv + (size_t)n * D3;
    const float* k = q + D_;
    const float* v = q + 2 * D_;
    int t = threadIdx.x;       // 256 threads, 4 elems each

    float4 qv = *(const float4*)&q[t * 4];
    float4 kv = *(const float4*)&k[t * 4];
    float qs  = qv.x + qv.y + qv.z + qv.w;
    float qs2 = qv.x*qv.x + qv.y*qv.y + qv.z*qv.z + qv.w*qv.w;
    float ks  = kv.x + kv.y + kv.z + kv.w;
    float ks2 = kv.x*kv.x + kv.y*kv.y + kv.z*kv.z + kv.w*kv.w;
    #pragma unroll
    for (int o = 16; o >= 1; o >>= 1) {
        qs  += __shfl_xor_sync(0xffffffffu, qs,  o);
        qs2 += __shfl_xor_sync(0xffffffffu, qs2, o);
        ks  += __shfl_xor_sync(0xffffffffu, ks,  o);
        ks2 += __shfl_xor_sync(0xffffffffu, ks2, o);
    }
    __shared__ float red[4][8];
    __shared__ float stat[4];
    __shared__ float qn[D_], kn[D_];
    int lane = t & 31, wp = t >> 5;
    if (lane == 0) { red[0][wp]=qs; red[1][wp]=qs2; red[2][wp]=ks; red[3][wp]=ks2; }
    __syncthreads();
    if (t == 0) {
        float a=0,c=0,e=0,f=0;
        #pragma unroll
        for (int i=0;i<8;i++){a+=red[0][i];c+=red[1][i];e+=red[2][i];f+=red[3][i];}
        float qmu=a*(1.f/D_), qvr=c*(1.f/D_)-qmu*qmu;
        float kmu=e*(1.f/D_), kvr=f*(1.f/D_)-kmu*kmu;
        stat[0]=qmu; stat[1]=rsqrtf(qvr+EPS);
        stat[2]=kmu; stat[3]=rsqrtf(kvr+EPS);
    }
    __syncthreads();
    float qmu=stat[0], qrs=stat[1], kmu=stat[2], krs=stat[3];
    float4 qwv = *(const float4*)&qw[t*4];
    float4 kwv = *(const float4*)&kw[t*4];
    qn[t*4+0]=(qv.x-qmu)*qrs*qwv.x; qn[t*4+1]=(qv.y-qmu)*qrs*qwv.y;
    qn[t*4+2]=(qv.z-qmu)*qrs*qwv.z; qn[t*4+3]=(qv.w-qmu)*qrs*qwv.w;
    kn[t*4+0]=(kv.x-kmu)*krs*kwv.x; kn[t*4+1]=(kv.y-kmu)*krs*kwv.y;
    kn[t*4+2]=(kv.z-kmu)*krs*kwv.z; kn[t*4+3]=(kv.w-kmu)*krs*kwv.w;
    __syncthreads();

    // rope + transpose-write. Elements d = t*4 .. t*4+3 share head h and j%4==0.
    int d0 = t * 4;
    int h  = d0 >> 6;
    int j0 = d0 & 63;
    float qo[4], ko[4];
    #pragma unroll
    for (int ii = 0; ii < 4; ii++) {
        int d = d0 + ii;
        int j = j0 + ii;
        int f = j & 31;
        float c = g_cos[l * 32 + f];
        float s = g_sin[l * 32 + f];
        if (j < 32) {
            qo[ii] = qn[d] * c - qn[d + 32] * s;
            ko[ii] = kn[d] * c - kn[d + 32] * s;
        } else {
            qo[ii] = qn[d] * c + qn[d - 32] * s;
            ko[ii] = kn[d] * c + kn[d - 32] * s;
        }
    }
    size_t oidx = ((((size_t)b * H_ + h) * L_) + l) * DH + j0;
    *(float4*)&g_qT[oidx] = make_float4(qo[0], qo[1], qo[2], qo[3]);
    *(float4*)&g_kT[oidx] = make_float4(ko[0], ko[1], ko[2], ko[3]);
    *(float4*)&g_vT[oidx] = *(const float4*)&v[d0];
}

// ---------------- flash attention (fp32) ----------------
// Block: (qtile 64 rows) x (head) x (batch). 256 threads, 4x4 register tile.
#define PS_STRIDE 68
#define ATT_SMEM_FLOATS (64*64*3 + 64*PS_STRIDE + 6*64 + 128)
#define ATT_SMEM_BYTES  (ATT_SMEM_FLOATS * 4)

__global__ __launch_bounds__(256) void attn_kernel(const int* __restrict__ seq_id) {
    extern __shared__ float sm[];
    float* Qt  = sm;                 // [d][r], stride 64
    float* Kt  = Qt + 64 * 64;       // [d][c], stride 64
    float* Vs  = Kt + 64 * 64;       // [c][dd], stride 64
    float* Ps  = Vs + 64 * 64;       // [r][c], stride PS_STRIDE
    float* mi  = Ps + 64 * PS_STRIDE;
    float* li  = mi  + 64;
    float* al  = li  + 64;
    float* mn  = al  + 64;
    float* tmx = mn  + 64;
    float* tsm = tmx + 64;
    int*   sq  = (int*)(tsm + 64);
    int*   sk  = sq + 64;

    int tid = threadIdx.x;
    int tx = tid & 15, ty = tid >> 4;
    int qt = blockIdx.x, h = blockIdx.y, b = blockIdx.z;
    int row0 = qt * 64;
    const float* qb = g_qT + (((size_t)(b * H_ + h)) * L_ + row0) * DH;
    const float* kb0 = g_kT + ((size_t)(b * H_ + h)) * L_ * DH;
    const float* vb0 = g_vT + ((size_t)(b * H_ + h)) * L_ * DH;

    // load Q transposed
    {
        int r = tid >> 2, d4 = (tid & 3) * 16;
        #pragma unroll
        for (int ii = 0; ii < 4; ii++) {
            int d = d4 + ii * 4;
            float4 q4 = *(const float4*)&qb[r * DH + d];
            Qt[(d+0)*64 + r] = q4.x; Qt[(d+1)*64 + r] = q4.y;
            Qt[(d+2)*64 + r] = q4.z; Qt[(d+3)*64 + r] = q4.w;
        }
    }
    if (tid < 64) {
        sq[tid] = seq_id[b * L_ + row0 + tid];
        mi[tid] = -1e30f;
        li[tid] = 0.0f;
    }
    float acc[4][4];
    #pragma unroll
    for (int i=0;i<4;i++)
        #pragma unroll
        for (int j=0;j<4;j++) acc[i][j]=0.f;
    __syncthreads();

    for (int mt = 0; mt < L_ / 64; mt++) {
        int col0 = mt * 64;
        const float* kbt = kb0 + (size_t)col0 * DH;
        const float* vbt = vb0 + (size_t)col0 * DH;
        {
            int c = tid >> 2, d4 = (tid & 3) * 16;
            #pragma unroll
            for (int ii = 0; ii < 4; ii++) {
                int d = d4 + ii * 4;
                float4 k4 = *(const float4*)&kbt[c * DH + d];
                Kt[(d+0)*64 + c] = k4.x; Kt[(d+1)*64 + c] = k4.y;
                Kt[(d+2)*64 + c] = k4.z; Kt[(d+3)*64 + c] = k4.w;
                *(float4*)&Vs[c * 64 + d] = *(const float4*)&vbt[c * DH + d];
            }
        }
        if (tid < 64) sk[tid] = seq_id[b * L_ + col0 + tid];
        __syncthreads();

        // S = Q K^T  (4x4 per thread)
        float s[4][4];
        #pragma unroll
        for (int i=0;i<4;i++)
            #pragma unroll
            for (int j=0;j<4;j++) s[i][j]=0.f;
        #pragma unroll
        for (int d = 0; d < 64; d++) {
            float4 q4 = *(const float4*)&Qt[d * 64 + ty * 4];
            float4 k4 = *(const float4*)&Kt[d * 64 + tx * 4];
            float qa[4] = {q4.x, q4.y, q4.z, q4.w};
            float ka[4] = {k4.x, k4.y, k4.z, k4.w};
            #pragma unroll
            for (int i=0;i<4;i++)
                #pragma unroll
                for (int j=0;j<4;j++)
                    s[i][j] = fmaf(qa[i], ka[j], s[i][j]);
        }
        // scale + mask
        const float scale = 0.125f;
        int myq[4], myk[4];
        #pragma unroll
        for (int i=0;i<4;i++) myq[i] = sq[ty*4+i];
        #pragma unroll
        for (int j=0;j<4;j++) myk[j] = sk[tx*4+j];
        #pragma unroll
        for (int i=0;i<4;i++)
            #pragma unroll
            for (int j=0;j<4;j++)
                s[i][j] = (myq[i] == myk[j]) ? s[i][j] * scale : -2e30f;

        // row-max over 16-lane tx group
        #pragma unroll
        for (int i=0;i<4;i++) {
            float m = fmaxf(fmaxf(s[i][0], s[i][1]), fmaxf(s[i][2], s[i][3]));
            #pragma unroll
            for (int o = 8; o >= 1; o >>= 1)
                m = fmaxf(m, __shfl_xor_sync(0xffffffffu, m, o));
            if (tx == 0) tmx[ty*4+i] = m;
        }
        __syncthreads();
        if (tid < 64) {
            float mo = mi[tid];
            float m2 = fmaxf(mo, tmx[tid]);
            al[tid] = __expf(mo - m2);
            mi[tid] = m2;
            mn[tid] = m2;
        }
        __syncthreads();

        // P = exp(S - m), write Ps, rescale acc, partial sums
        #pragma unroll
        for (int i=0;i<4;i++) {
            float m2 = mn[ty*4+i];
            float p0 = __expf(s[i][0] - m2);
            float p1 = __expf(s[i][1] - m2);
            float p2 = __expf(s[i][2] - m2);
            float p3 = __expf(s[i][3] - m2);
            *(float4*)&Ps[(ty*4+i) * PS_STRIDE + tx*4] = make_float4(p0,p1,p2,p3);
            float rs = p0 + p1 + p2 + p3;
            #pragma unroll
            for (int o = 8; o >= 1; o >>= 1)
                rs += __shfl_xor_sync(0xffffffffu, rs, o);
            if (tx == 0) tsm[ty*4+i] = rs;
            float a = al[ty*4+i];
            #pragma unroll
            for (int j=0;j<4;j++) acc[i][j] *= a;
        }
        __syncthreads();
        if (tid < 64) li[tid] = li[tid] * al[tid] + tsm[tid];

        // acc += P @ V
        #pragma unroll
        for (int c = 0; c < 64; c++) {
            float4 v4 = *(const float4*)&Vs[c * 64 + tx * 4];
            float va[4] = {v4.x, v4.y, v4.z, v4.w};
            float pa[4];
            #pragma unroll
            for (int i=0;i<4;i++) pa[i] = Ps[(ty*4+i) * PS_STRIDE + c];
            #pragma unroll
            for (int i=0;i<4;i++)
                #pragma unroll
                for (int j=0;j<4;j++)
                    acc[i][j] = fmaf(pa[i], va[j], acc[i][j]);
        }
        __syncthreads();
    }

    // epilogue: ctx[b, l, h, dd] = acc / l
    #pragma unroll
    for (int i=0;i<4;i++) {
        float inv = 1.0f / li[ty*4+i];
        int r = row0 + ty*4 + i;
        size_t o = (((size_t)b * L_ + r) * H_ + h) * DH + tx * 4;
        *(float4*)&g_ctx[o] = make_float4(acc[i][0]*inv, acc[i][1]*inv,
                                          acc[i][2]*inv, acc[i][3]*inv);
    }
}

// ---------------- launch ----------------
extern "C" void kernel_launch(void* const* d_in, const int* in_sizes, int n_in,
                              void* d_out, int out_size) {
    const float* x      = (const float*)d_in[0];
    const int*   seq_id = (const int*)  d_in[1];
    const float* ln1_w  = (const float*)d_in[2];
    const float* ln1_b  = (const float*)d_in[3];
    const float* w_qkv  = (const float*)d_in[4];
    const float* q_ln_w = (const float*)d_in[5];
    const float* k_ln_w = (const float*)d_in[6];
    const float* out_w  = (const float*)d_in[7];
    float* out = (float*)d_out;

    void *ph, *pqkv, *pctx;
    cudaGetSymbolAddress(&ph,   g_h);
    cudaGetSymbolAddress(&pqkv, g_qkv);
    cudaGetSymbolAddress(&pctx, g_ctx);

    cudaFuncSetAttribute(attn_kernel, cudaFuncAttributeMaxDynamicSharedMemorySize,
                         ATT_SMEM_BYTES);

    rope_table_kernel<<<(L_ * 32 + 255) / 256, 256>>>();
    ln1_kernel<<<NT, 256>>>(x, ln1_w, ln1_b);
    sgemm_nt<<<dim3(D3 / 128, NT / 128), 256>>>((const float*)ph, w_qkv,
                                                (float*)pqkv, NT, D3, D_);
    qk_rope_kernel<<<NT, 256>>>(q_ln_w, k_ln_w);
    attn_kernel<<<dim3(L_ / 64, H_, B_), 256, ATT_SMEM_BYTES>>>(seq_id);
    sgemm_nt<<<dim3(D_ / 128, NT / 128), 256>>>((const float*)pctx, out_w,
                                                out, NT, D_, D_);
}

// round 3
// speedup vs baseline: 1.0599x; 1.0599x over previous
#include <cuda_runtime.h>
#include <cuda_bf16.h>
#include <math.h>

// Problem constants
#define B_  2
#define L_  2048
#define NT  4096            // B*L tokens
#define D_  1024
#define H_  16
#define DH  64
#define D3  3072
#define EPS 1e-5f

typedef unsigned long long ull;

// ---------------- f32x2 packed helpers (Blackwell FFMA2 path) ----------------
__device__ __forceinline__ ull pk2(float x, float y) {
    ull r;
    asm("mov.b64 %0, {%1, %2};" : "=l"(r) : "f"(x), "f"(y));
    return r;
}
__device__ __forceinline__ void fma2(ull& d, ull a, ull b) {
    asm("fma.rn.f32x2 %0, %1, %2, %0;" : "+l"(d) : "l"(a), "l"(b));
}
__device__ __forceinline__ ull mul2(ull a, ull b) {
    ull r;
    asm("mul.rn.f32x2 %0, %1, %2;" : "=l"(r) : "l"(a), "l"(b));
    return r;
}
__device__ __forceinline__ float2 upk(ull v) {
    float2 r;
    asm("mov.b64 {%0, %1}, %2;" : "=f"(r.x), "=f"(r.y) : "l"(v));
    return r;
}

// ---------------- scratch (device globals; no allocation) ----------------
__device__ float g_h[NT * D_];        // LN1 output            [NT, D]
__device__ float g_qkv[NT * D3];      // QKV gemm output       [NT, 3D]
__device__ float g_qT[NT * D_];       // [B,H,L,DH]
__device__ float g_kT[NT * D_];       // [B,H,L,DH]
__device__ float g_vT[NT * D_];       // [B,H,L,DH]
__device__ float g_ctx[NT * D_];      // [B,L,H,DH] == [NT, D]
__device__ float g_cos[L_ * 32];
__device__ float g_sin[L_ * 32];

// ---------------- RoPE table ----------------
__global__ void rope_table_kernel() {
    int idx = blockIdx.x * blockDim.x + threadIdx.x;   // 0 .. 2048*32-1
    if (idx >= L_ * 32) return;
    int l = idx >> 5;
    int j = idx & 31;
    float inv = powf(10000.0f, -(float)j / 32.0f);
    float ang = (float)l * inv;
    float s, c;
    sincosf(ang, &s, &c);
    g_cos[idx] = c;
    g_sin[idx] = s;
}

// ---------------- LN1: y = (x-mu)*rstd*w + b ----------------
__global__ void ln1_kernel(const float* __restrict__ x,
                           const float* __restrict__ w,
                           const float* __restrict__ b) {
    int n = blockIdx.x;
    const float* xr = x + (size_t)n * D_;
    int t = threadIdx.x;                      // 256 threads, 4 elems each
    float4 v = *(const float4*)&xr[t * 4];
    float s  = v.x + v.y + v.z + v.w;
    float s2 = v.x*v.x + v.y*v.y + v.z*v.z + v.w*v.w;
    #pragma unroll
    for (int o = 16; o >= 1; o >>= 1) {
        s  += __shfl_xor_sync(0xffffffffu, s,  o);
        s2 += __shfl_xor_sync(0xffffffffu, s2, o);
    }
    __shared__ float red[2][8];
    int lane = t & 31, wp = t >> 5;
    if (lane == 0) { red[0][wp] = s; red[1][wp] = s2; }
    __syncthreads();
    __shared__ float stat[2];
    if (t == 0) {
        float a = 0.f, c = 0.f;
        #pragma unroll
        for (int i = 0; i < 8; i++) { a += red[0][i]; c += red[1][i]; }
        float mu  = a * (1.0f / D_);
        float var = c * (1.0f / D_) - mu * mu;
        stat[0] = mu;
        stat[1] = rsqrtf(var + EPS);
    }
    __syncthreads();
    float mu = stat[0], rs = stat[1];
    float4 wv = *(const float4*)&w[t * 4];
    float4 bv = *(const float4*)&b[t * 4];
    float4 o;
    o.x = (v.x - mu) * rs * wv.x + bv.x;
    o.y = (v.y - mu) * rs * wv.y + bv.y;
    o.z = (v.z - mu) * rs * wv.z + bv.z;
    o.w = (v.w - mu) * rs * wv.w + bv.w;
    *(float4*)&g_h[(size_t)n * D_ + t * 4] = o;
}

// ---------------- generic SGEMM: C[M,N] = A[M,K] * B[N,K]^T ----------------
// BM=BN=128, BK=8, 256 threads, 8x8 per thread, f32x2 packed FMA inner loop.
__global__ __launch_bounds__(256) void sgemm_nt(const float* __restrict__ A,
                                                const float* __restrict__ Bm,
                                                float* __restrict__ C,
                                                int M, int N, int K) {
    __shared__ float As[8][128];
    __shared__ float Bs[8][128];
    int tid = threadIdx.x;
    int tx = tid & 15, ty = tid >> 4;
    int row0 = blockIdx.y * 128, col0 = blockIdx.x * 128;
    int lr = tid >> 1;            // 0..127
    int lc = (tid & 1) * 4;       // 0 or 4

    const float* Ag = A  + (size_t)(row0 + lr) * K + lc;
    const float* Bg = Bm + (size_t)(col0 + lr) * K + lc;

    ull acc2[8][4];
    #pragma unroll
    for (int i = 0; i < 8; i++)
        #pragma unroll
        for (int j = 0; j < 4; j++) acc2[i][j] = 0ULL;   // {0.f, 0.f}

    for (int k0 = 0; k0 < K; k0 += 8) {
        float4 a = *(const float4*)(Ag + k0);
        float4 b = *(const float4*)(Bg + k0);
        As[lc+0][lr] = a.x; As[lc+1][lr] = a.y; As[lc+2][lr] = a.z; As[lc+3][lr] = a.w;
        Bs[lc+0][lr] = b.x; Bs[lc+1][lr] = b.y; Bs[lc+2][lr] = b.z; Bs[lc+3][lr] = b.w;
        __syncthreads();
        #pragma unroll
        for (int kk = 0; kk < 8; kk++) {
            float4 a0 = *(const float4*)&As[kk][ty * 8];
            float4 a1 = *(const float4*)&As[kk][ty * 8 + 4];
            const ull* bp = (const ull*)&Bs[kk][tx * 8];
            ull pb0 = bp[0], pb1 = bp[1], pb2 = bp[2], pb3 = bp[3];
            float am[8] = {a0.x, a0.y, a0.z, a0.w, a1.x, a1.y, a1.z, a1.w};
            #pragma unroll
            for (int i = 0; i < 8; i++) {
                ull pa = pk2(am[i], am[i]);
                fma2(acc2[i][0], pa, pb0);
                fma2(acc2[i][1], pa, pb1);
                fma2(acc2[i][2], pa, pb2);
                fma2(acc2[i][3], pa, pb3);
            }
        }
        __syncthreads();
    }
    #pragma unroll
    for (int i = 0; i < 8; i++) {
        float2 p0 = upk(acc2[i][0]);
        float2 p1 = upk(acc2[i][1]);
        float2 p2 = upk(acc2[i][2]);
        float2 p3 = upk(acc2[i][3]);
        size_t r = (size_t)(row0 + ty * 8 + i) * N + col0 + tx * 8;
        *(float4*)&C[r]     = make_float4(p0.x, p0.y, p1.x, p1.y);
        *(float4*)&C[r + 4] = make_float4(p2.x, p2.y, p3.x, p3.y);
    }
}

// ---------------- fused QK-LN + RoPE + transpose + V copy ----------------
__global__ void qk_rope_kernel(const float* __restrict__ qw,
                               const float* __restrict__ kw) {
    int n = blockIdx.x;
    int b = n >> 11;           // / 2048
    int l = n & 2047;
    const float* q = g_qkv + (size_t)n * D3;
    const float* k = q + D_;
    const float* v = q + 2 * D_;
    int t = threadIdx.x;       // 256 threads, 4 elems each

    float4 qv = *(const float4*)&q[t * 4];
    float4 kv = *(const float4*)&k[t * 4];
    float qs  = qv.x + qv.y + qv.z + qv.w;
    float qs2 = qv.x*qv.x + qv.y*qv.y + qv.z*qv.z + qv.w*qv.w;
    float ks  = kv.x + kv.y + kv.z + kv.w;
    float ks2 = kv.x*kv.x + kv.y*kv.y + kv.z*kv.z + kv.w*kv.w;
    #pragma unroll
    for (int o = 16; o >= 1; o >>= 1) {
        qs  += __shfl_xor_sync(0xffffffffu, qs,  o);
        qs2 += __shfl_xor_sync(0xffffffffu, qs2, o);
        ks  += __shfl_xor_sync(0xffffffffu, ks,  o);
        ks2 += __shfl_xor_sync(0xffffffffu, ks2, o);
    }
    __shared__ float red[4][8];
    __shared__ float stat[4];
    __shared__ float qn[D_], kn[D_];
    int lane = t & 31, wp = t >> 5;
    if (lane == 0) { red[0][wp]=qs; red[1][wp]=qs2; red[2][wp]=ks; red[3][wp]=ks2; }
    __syncthreads();
    if (t == 0) {
        float a=0,c=0,e=0,f=0;
        #pragma unroll
        for (int i=0;i<8;i++){a+=red[0][i];c+=red[1][i];e+=red[2][i];f+=red[3][i];}
        float qmu=a*(1.f/D_), qvr=c*(1.f/D_)-qmu*qmu;
        float kmu=e*(1.f/D_), kvr=f*(1.f/D_)-kmu*kmu;
        stat[0]=qmu; stat[1]=rsqrtf(qvr+EPS);
        stat[2]=kmu; stat[3]=rsqrtf(kvr+EPS);
    }
    __syncthreads();
    float qmu=stat[0], qrs=stat[1], kmu=stat[2], krs=stat[3];
    float4 qwv = *(const float4*)&qw[t*4];
    float4 kwv = *(const float4*)&kw[t*4];
    qn[t*4+0]=(qv.x-qmu)*qrs*qwv.x; qn[t*4+1]=(qv.y-qmu)*qrs*qwv.y;
    qn[t*4+2]=(qv.z-qmu)*qrs*qwv.z; qn[t*4+3]=(qv.w-qmu)*qrs*qwv.w;
    kn[t*4+0]=(kv.x-kmu)*krs*kwv.x; kn[t*4+1]=(kv.y-kmu)*krs*kwv.y;
    kn[t*4+2]=(kv.z-kmu)*krs*kwv.z; kn[t*4+3]=(kv.w-kmu)*krs*kwv.w;
    __syncthreads();

    // rope + transpose-write. Elements d = t*4 .. t*4+3 share head h and j%4==0.
    int d0 = t * 4;
    int h  = d0 >> 6;
    int j0 = d0 & 63;
    float qo[4], ko[4];
    #pragma unroll
    for (int ii = 0; ii < 4; ii++) {
        int d = d0 + ii;
        int j = j0 + ii;
        int f = j & 31;
        float c = g_cos[l * 32 + f];
        float s = g_sin[l * 32 + f];
        if (j < 32) {
            qo[ii] = qn[d] * c - qn[d + 32] * s;
            ko[ii] = kn[d] * c - kn[d + 32] * s;
        } else {
            qo[ii] = qn[d] * c + qn[d - 32] * s;
            ko[ii] = kn[d] * c + kn[d - 32] * s;
        }
    }
    size_t oidx = ((((size_t)b * H_ + h) * L_) + l) * DH + j0;
    *(float4*)&g_qT[oidx] = make_float4(qo[0], qo[1], qo[2], qo[3]);
    *(float4*)&g_kT[oidx] = make_float4(ko[0], ko[1], ko[2], ko[3]);
    *(float4*)&g_vT[oidx] = *(const float4*)&v[d0];
}

// ---------------- flash attention (fp32, f32x2 mainloops) ----------------
// Block: (qtile 64 rows) x (head) x (batch). 256 threads, 4x4 register tile.
#define PS_STRIDE 68
#define ATT_SMEM_FLOATS (64*64*3 + 64*PS_STRIDE + 6*64 + 128)
#define ATT_SMEM_BYTES  (ATT_SMEM_FLOATS * 4)

__global__ __launch_bounds__(256) void attn_kernel(const int* __restrict__ seq_id) {
    extern __shared__ float sm[];
    float* Qt  = sm;                 // [d][r], stride 64
    float* Kt  = Qt + 64 * 64;       // [d][c], stride 64
    float* Vs  = Kt + 64 * 64;       // [c][dd], stride 64
    float* Ps  = Vs + 64 * 64;       // [r][c], stride PS_STRIDE
    float* mi  = Ps + 64 * PS_STRIDE;
    float* li  = mi  + 64;
    float* al  = li  + 64;
    float* mn  = al  + 64;
    float* tmx = mn  + 64;
    float* tsm = tmx + 64;
    int*   sq  = (int*)(tsm + 64);
    int*   sk  = sq + 64;

    int tid = threadIdx.x;
    int tx = tid & 15, ty = tid >> 4;
    int qt = blockIdx.x, h = blockIdx.y, b = blockIdx.z;
    int row0 = qt * 64;
    const float* qb = g_qT + (((size_t)(b * H_ + h)) * L_ + row0) * DH;
    const float* kb0 = g_kT + ((size_t)(b * H_ + h)) * L_ * DH;
    const float* vb0 = g_vT + ((size_t)(b * H_ + h)) * L_ * DH;

    // load Q transposed
    {
        int r = tid >> 2, d4 = (tid & 3) * 16;
        #pragma unroll
        for (int ii = 0; ii < 4; ii++) {
            int d = d4 + ii * 4;
            float4 q4 = *(const float4*)&qb[r * DH + d];
            Qt[(d+0)*64 + r] = q4.x; Qt[(d+1)*64 + r] = q4.y;
            Qt[(d+2)*64 + r] = q4.z; Qt[(d+3)*64 + r] = q4.w;
        }
    }
    if (tid < 64) {
        sq[tid] = seq_id[b * L_ + row0 + tid];
        mi[tid] = -1e30f;
        li[tid] = 0.0f;
    }
    ull acc2[4][2];
    #pragma unroll
    for (int i=0;i<4;i++) { acc2[i][0] = 0ULL; acc2[i][1] = 0ULL; }
    __syncthreads();

    for (int mt = 0; mt < L_ / 64; mt++) {
        int col0 = mt * 64;
        const float* kbt = kb0 + (size_t)col0 * DH;
        const float* vbt = vb0 + (size_t)col0 * DH;
        {
            int c = tid >> 2, d4 = (tid & 3) * 16;
            #pragma unroll
            for (int ii = 0; ii < 4; ii++) {
                int d = d4 + ii * 4;
                float4 k4 = *(const float4*)&kbt[c * DH + d];
                Kt[(d+0)*64 + c] = k4.x; Kt[(d+1)*64 + c] = k4.y;
                Kt[(d+2)*64 + c] = k4.z; Kt[(d+3)*64 + c] = k4.w;
                *(float4*)&Vs[c * 64 + d] = *(const float4*)&vbt[c * DH + d];
            }
        }
        if (tid < 64) sk[tid] = seq_id[b * L_ + col0 + tid];
        __syncthreads();

        // S = Q K^T  (4x4 per thread, packed pairs along columns)
        ull s2[4][2];
        #pragma unroll
        for (int i=0;i<4;i++) { s2[i][0] = 0ULL; s2[i][1] = 0ULL; }
        #pragma unroll
        for (int d = 0; d < 64; d++) {
            float4 q4 = *(const float4*)&Qt[d * 64 + ty * 4];
            const ull* kp = (const ull*)&Kt[d * 64 + tx * 4];
            ull kb0p = kp[0], kb1p = kp[1];
            float qa[4] = {q4.x, q4.y, q4.z, q4.w};
            #pragma unroll
            for (int i=0;i<4;i++) {
                ull pq = pk2(qa[i], qa[i]);
                fma2(s2[i][0], pq, kb0p);
                fma2(s2[i][1], pq, kb1p);
            }
        }
        // unpack, scale + mask
        float s[4][4];
        #pragma unroll
        for (int i=0;i<4;i++) {
            float2 u0 = upk(s2[i][0]);
            float2 u1 = upk(s2[i][1]);
            s[i][0] = u0.x; s[i][1] = u0.y; s[i][2] = u1.x; s[i][3] = u1.y;
        }
        const float scale = 0.125f;
        int myq[4], myk[4];
        #pragma unroll
        for (int i=0;i<4;i++) myq[i] = sq[ty*4+i];
        #pragma unroll
        for (int j=0;j<4;j++) myk[j] = sk[tx*4+j];
        #pragma unroll
        for (int i=0;i<4;i++)
            #pragma unroll
            for (int j=0;j<4;j++)
                s[i][j] = (myq[i] == myk[j]) ? s[i][j] * scale : -2e30f;

        // row-max over 16-lane tx group
        #pragma unroll
        for (int i=0;i<4;i++) {
            float m = fmaxf(fmaxf(s[i][0], s[i][1]), fmaxf(s[i][2], s[i][3]));
            #pragma unroll
            for (int o = 8; o >= 1; o >>= 1)
                m = fmaxf(m, __shfl_xor_sync(0xffffffffu, m, o));
            if (tx == 0) tmx[ty*4+i] = m;
        }
        __syncthreads();
        if (tid < 64) {
            float mo = mi[tid];
            float m2 = fmaxf(mo, tmx[tid]);
            al[tid] = __expf(mo - m2);
            mi[tid] = m2;
            mn[tid] = m2;
        }
        __syncthreads();

        // P = exp(S - m), write Ps, rescale acc, partial sums
        #pragma unroll
        for (int i=0;i<4;i++) {
            float m2 = mn[ty*4+i];
            float p0 = __expf(s[i][0] - m2);
            float p1 = __expf(s[i][1] - m2);
            float p2 = __expf(s[i][2] - m2);
            float p3 = __expf(s[i][3] - m2);
            *(float4*)&Ps[(ty*4+i) * PS_STRIDE + tx*4] = make_float4(p0,p1,p2,p3);
            float rs = p0 + p1 + p2 + p3;
            #pragma unroll
            for (int o = 8; o >= 1; o >>= 1)
                rs += __shfl_xor_sync(0xffffffffu, rs, o);
            if (tx == 0) tsm[ty*4+i] = rs;
            float a = al[ty*4+i];
            ull aa = pk2(a, a);
            acc2[i][0] = mul2(acc2[i][0], aa);
            acc2[i][1] = mul2(acc2[i][1], aa);
        }
        __syncthreads();
        if (tid < 64) li[tid] = li[tid] * al[tid] + tsm[tid];

        // acc += P @ V  (packed pairs along dd)
        #pragma unroll
        for (int c = 0; c < 64; c++) {
            const ull* vp = (const ull*)&Vs[c * 64 + tx * 4];
            ull vb0p = vp[0], vb1p = vp[1];
            #pragma unroll
            for (int i=0;i<4;i++) {
                float p = Ps[(ty*4+i) * PS_STRIDE + c];
                ull pp = pk2(p, p);
                fma2(acc2[i][0], pp, vb0p);
                fma2(acc2[i][1], pp, vb1p);
            }
        }
        __syncthreads();
    }

    // epilogue: ctx[b, l, h, dd] = acc / l
    #pragma unroll
    for (int i=0;i<4;i++) {
        float inv = 1.0f / li[ty*4+i];
        int r = row0 + ty*4 + i;
        size_t o = (((size_t)b * L_ + r) * H_ + h) * DH + tx * 4;
        float2 u0 = upk(acc2[i][0]);
        float2 u1 = upk(acc2[i][1]);
        *(float4*)&g_ctx[o] = make_float4(u0.x*inv, u0.y*inv, u1.x*inv, u1.y*inv);
    }
}

// ---------------- launch ----------------
extern "C" void kernel_launch(void* const* d_in, const int* in_sizes, int n_in,
                              void* d_out, int out_size) {
    const float* x      = (const float*)d_in[0];
    const int*   seq_id = (const int*)  d_in[1];
    const float* ln1_w  = (const float*)d_in[2];
    const float* ln1_b  = (const float*)d_in[3];
    const float* w_qkv  = (const float*)d_in[4];
    const float* q_ln_w = (const float*)d_in[5];
    const float* k_ln_w = (const float*)d_in[6];
    const float* out_w  = (const float*)d_in[7];
    float* out = (float*)d_out;

    void *ph, *pqkv, *pctx;
    cudaGetSymbolAddress(&ph,   g_h);
    cudaGetSymbolAddress(&pqkv, g_qkv);
    cudaGetSymbolAddress(&pctx, g_ctx);

    cudaFuncSetAttribute(attn_kernel, cudaFuncAttributeMaxDynamicSharedMemorySize,
                         ATT_SMEM_BYTES);

    rope_table_kernel<<<(L_ * 32 + 255) / 256, 256>>>();
    ln1_kernel<<<NT, 256>>>(x, ln1_w, ln1_b);
    sgemm_nt<<<dim3(D3 / 128, NT / 128), 256>>>((const float*)ph, w_qkv,
                                                (float*)pqkv, NT, D3, D_);
    qk_rope_kernel<<<NT, 256>>>(q_ln_w, k_ln_w);
    attn_kernel<<<dim3(L_ / 64, H_, B_), 256, ATT_SMEM_BYTES>>>(seq_id);
    sgemm_nt<<<dim3(D_ / 128, NT / 128), 256>>>((const float*)pctx, out_w,
                                                out, NT, D_, D_);
}

// round 5
// speedup vs baseline: 1.3486x; 1.2724x over previous
#include <cuda_runtime.h>
#include <cuda_bf16.h>
#include <cstdint>
#include <math.h>

// Problem constants
#define B_  2
#define L_  2048
#define NT  4096            // B*L tokens
#define D_  1024
#define H_  16
#define DH  64
#define D3  3072
#define EPS 1e-5f

typedef unsigned long long ull;

// ---------------- f32x2 packed helpers (attention mainloops) ----------------
__device__ __forceinline__ ull pk2(float x, float y) {
    ull r;
    asm("mov.b64 %0, {%1, %2};" : "=l"(r) : "f"(x), "f"(y));
    return r;
}
__device__ __forceinline__ void fma2(ull& d, ull a, ull b) {
    asm("fma.rn.f32x2 %0, %1, %2, %0;" : "+l"(d) : "l"(a), "l"(b));
}
__device__ __forceinline__ ull mul2(ull a, ull b) {
    ull r;
    asm("mul.rn.f32x2 %0, %1, %2;" : "=l"(r) : "l"(a), "l"(b));
    return r;
}
__device__ __forceinline__ float2 upk(ull v) {
    float2 r;
    asm("mov.b64 {%0, %1}, %2;" : "=f"(r.x), "=f"(r.y) : "l"(v));
    return r;
}

// ---------------- scratch (device globals; no allocation) ----------------
__device__ __nv_bfloat16 g_hh[NT * D_];   // LN1 out hi
__device__ __nv_bfloat16 g_hl[NT * D_];   // LN1 out lo
__device__ __nv_bfloat16 g_wqh[D3 * D_];  // w_qkv hi
__device__ __nv_bfloat16 g_wql[D3 * D_];  // w_qkv lo
__device__ __nv_bfloat16 g_owh[D_ * D_];  // out_w hi
__device__ __nv_bfloat16 g_owl[D_ * D_];  // out_w lo
__device__ __nv_bfloat16 g_ch[NT * D_];   // ctx hi   [B,L,H,DH] == [NT,D]
__device__ __nv_bfloat16 g_cl[NT * D_];   // ctx lo
__device__ float g_qkv[NT * D3];          // QKV gemm output [NT, 3D]
__device__ float g_qT[NT * D_];           // [B,H,L,DH]
__device__ float g_kT[NT * D_];
__device__ float g_vT[NT * D_];
__device__ float g_cos[L_ * 32];
__device__ float g_sin[L_ * 32];

// ---------------- cp.async helpers ----------------
__device__ __forceinline__ uint32_t smem_u32(const void* p) {
    uint32_t a;
    asm("{ .reg .u64 t; cvta.to.shared.u64 t, %1; cvt.u32.u64 %0, t; }"
        : "=r"(a) : "l"(p));
    return a;
}
#define CP_ASYNC16(dst, src) \
    asm volatile("cp.async.cg.shared.global [%0], [%1], 16;" :: "r"(dst), "l"(src))
#define CP_COMMIT() asm volatile("cp.async.commit_group;" ::: "memory")
#define CP_WAIT0()  asm volatile("cp.async.wait_group 0;" ::: "memory")
#define CP_WAIT1()  asm volatile("cp.async.wait_group 1;" ::: "memory")

// mma.sync m16n8k16 bf16 -> fp32 (legacy HMMA path, valid on compute_103)
#define MMA16816(d, a, b) \
    asm volatile( \
        "mma.sync.aligned.m16n8k16.row.col.f32.bf16.bf16.f32 " \
        "{%0,%1,%2,%3}, {%4,%5,%6,%7}, {%8,%9}, {%0,%1,%2,%3};" \
        : "+f"((d)[0]), "+f"((d)[1]), "+f"((d)[2]), "+f"((d)[3]) \
        : "r"((a)[0]), "r"((a)[1]), "r"((a)[2]), "r"((a)[3]), \
          "r"((b)[0]), "r"((b)[1]))

// ---------------- RoPE table ----------------
__global__ void rope_table_kernel() {
    int idx = blockIdx.x * blockDim.x + threadIdx.x;
    if (idx >= L_ * 32) return;
    int l = idx >> 5;
    int j = idx & 31;
    float inv = powf(10000.0f, -(float)j / 32.0f);
    float ang = (float)l * inv;
    float s, c;
    sincosf(ang, &s, &c);
    g_cos[idx] = c;
    g_sin[idx] = s;
}

// ---------------- hi/lo bf16 split for weights ----------------
__global__ void split_kernel(const float* __restrict__ x,
                             __nv_bfloat16* __restrict__ hi,
                             __nv_bfloat16* __restrict__ lo) {
    int i = (blockIdx.x * 256 + threadIdx.x) * 4;
    float4 v = *(const float4*)&x[i];
    float vv[4] = {v.x, v.y, v.z, v.w};
    union { __nv_bfloat16 h[4]; uint2 u; } a, b;
    #pragma unroll
    for (int j = 0; j < 4; j++) {
        __nv_bfloat16 hb = __float2bfloat16(vv[j]);
        a.h[j] = hb;
        b.h[j] = __float2bfloat16(vv[j] - __bfloat162float(hb));
    }
    *(uint2*)&hi[i] = a.u;
    *(uint2*)&lo[i] = b.u;
}

// ---------------- LN1: y = (x-mu)*rstd*w + b  ->  bf16 hi/lo ----------------
__global__ void ln1_kernel(const float* __restrict__ x,
                           const float* __restrict__ w,
                           const float* __restrict__ b) {
    int n = blockIdx.x;
    const float* xr = x + (size_t)n * D_;
    int t = threadIdx.x;
    float4 v = *(const float4*)&xr[t * 4];
    float s  = v.x + v.y + v.z + v.w;
    float s2 = v.x*v.x + v.y*v.y + v.z*v.z + v.w*v.w;
    #pragma unroll
    for (int o = 16; o >= 1; o >>= 1) {
        s  += __shfl_xor_sync(0xffffffffu, s,  o);
        s2 += __shfl_xor_sync(0xffffffffu, s2, o);
    }
    __shared__ float red[2][8];
    int lane = t & 31, wp = t >> 5;
    if (lane == 0) { red[0][wp] = s; red[1][wp] = s2; }
    __syncthreads();
    __shared__ float stat[2];
    if (t == 0) {
        float a = 0.f, c = 0.f;
        #pragma unroll
        for (int i = 0; i < 8; i++) { a += red[0][i]; c += red[1][i]; }
        float mu  = a * (1.0f / D_);
        float var = c * (1.0f / D_) - mu * mu;
        stat[0] = mu;
        stat[1] = rsqrtf(var + EPS);
    }
    __syncthreads();
    float mu = stat[0], rs = stat[1];
    float4 wv = *(const float4*)&w[t * 4];
    float4 bv = *(const float4*)&b[t * 4];
    float oo[4];
    oo[0] = (v.x - mu) * rs * wv.x + bv.x;
    oo[1] = (v.y - mu) * rs * wv.y + bv.y;
    oo[2] = (v.z - mu) * rs * wv.z + bv.z;
    oo[3] = (v.w - mu) * rs * wv.w + bv.w;
    union { __nv_bfloat16 h[4]; uint2 u; } a, bb;
    #pragma unroll
    for (int j = 0; j < 4; j++) {
        __nv_bfloat16 hb = __float2bfloat16(oo[j]);
        a.h[j]  = hb;
        bb.h[j] = __float2bfloat16(oo[j] - __bfloat162float(hb));
    }
    size_t oidx = (size_t)n * D_ + t * 4;
    *(uint2*)&g_hh[oidx] = a.u;
    *(uint2*)&g_hl[oidx] = bb.u;
}

// ============ warp-MMA bf16 split-3 GEMM: C[M,N] = A[M,K]*B[N,K]^T (fp32) ============
// CTA 128x128, 8 warps of 64x32, K-step 16, cp.async double buffer.
__global__ __launch_bounds__(256) void gemm_mma(
    const __nv_bfloat16* __restrict__ Ah, const __nv_bfloat16* __restrict__ Al,
    const __nv_bfloat16* __restrict__ Bh, const __nv_bfloat16* __restrict__ Bl,
    float* __restrict__ C, int M, int N, int K)
{
    __shared__ __nv_bfloat16 sA[2][2][128 * 16];
    __shared__ __nv_bfloat16 sB[2][2][128 * 16];

    int tid = threadIdx.x;
    int warp = tid >> 5, lane = tid & 31;
    int m0 = blockIdx.y * 128, n0 = blockIdx.x * 128;
    int wm = (warp & 1) * 64, wn = (warp >> 1) * 32;

    int lrow = tid >> 1;          // 0..127
    int lch  = (tid & 1) * 8;     // 0 or 8 (bf16 elems; 16B chunk)

    const __nv_bfloat16* gA[2] = {Ah + (size_t)(m0 + lrow) * K + lch,
                                  Al + (size_t)(m0 + lrow) * K + lch};
    const __nv_bfloat16* gB[2] = {Bh + (size_t)(n0 + lrow) * K + lch,
                                  Bl + (size_t)(n0 + lrow) * K + lch};

    float d[4][4][4];
    #pragma unroll
    for (int mi = 0; mi < 4; mi++)
        #pragma unroll
        for (int ni = 0; ni < 4; ni++)
            #pragma unroll
            for (int r = 0; r < 4; r++) d[mi][ni][r] = 0.f;

    const int nstep = K >> 4;

    // ---- prologue: stages 0 and 1 ----
    #pragma unroll
    for (int s = 0; s < 2; s++) {
        int st = s & 1;
        #pragma unroll
        for (int sp = 0; sp < 2; sp++) {
            CP_ASYNC16(smem_u32(&sA[st][sp][lrow * 16 + lch]), gA[sp] + s * 16);
            CP_ASYNC16(smem_u32(&sB[st][sp][lrow * 16 + lch]), gB[sp] + s * 16);
        }
        CP_COMMIT();
    }

    int ar = wm + (lane >> 2);        // A rows base
    int ac = (lane & 3) * 2;          // A k base
    int br = wn + (lane >> 2);        // B n base
    int bc = (lane & 3) * 2;          // B k base

    for (int s = 0; s < nstep; s++) {
        int st = s & 1;
        if (s == nstep - 1) { CP_WAIT0(); } else { CP_WAIT1(); }
        __syncthreads();

        const __nv_bfloat16* pAh = &sA[st][0][0];
        const __nv_bfloat16* pAl = &sA[st][1][0];
        const __nv_bfloat16* pBh = &sB[st][0][0];
        const __nv_bfloat16* pBl = &sB[st][1][0];

        uint32_t ah[4][4], al[4][4], bh[4][2], bl[4][2];
        #pragma unroll
        for (int mi = 0; mi < 4; mi++) {
            int r0 = (ar + mi * 16) * 16 + ac;
            int r1 = r0 + 8 * 16;
            ah[mi][0] = *(const uint32_t*)(pAh + r0);
            ah[mi][1] = *(const uint32_t*)(pAh + r1);
            ah[mi][2] = *(const uint32_t*)(pAh + r0 + 8);
            ah[mi][3] = *(const uint32_t*)(pAh + r1 + 8);
            al[mi][0] = *(const uint32_t*)(pAl + r0);
            al[mi][1] = *(const uint32_t*)(pAl + r1);
            al[mi][2] = *(const uint32_t*)(pAl + r0 + 8);
            al[mi][3] = *(const uint32_t*)(pAl + r1 + 8);
        }
        #pragma unroll
        for (int ni = 0; ni < 4; ni++) {
            int c0 = (br + ni * 8) * 16 + bc;
            bh[ni][0] = *(const uint32_t*)(pBh + c0);
            bh[ni][1] = *(const uint32_t*)(pBh + c0 + 8);
            bl[ni][0] = *(const uint32_t*)(pBl + c0);
            bl[ni][1] = *(const uint32_t*)(pBl + c0 + 8);
        }

        #pragma unroll
        for (int mi = 0; mi < 4; mi++)
            #pragma unroll
            for (int ni = 0; ni < 4; ni++) {
                MMA16816(d[mi][ni], ah[mi], bh[ni]);
                MMA16816(d[mi][ni], ah[mi], bl[ni]);
                MMA16816(d[mi][ni], al[mi], bh[ni]);
            }

        __syncthreads();
        if (s + 2 < nstep) {
            #pragma unroll
            for (int sp = 0; sp < 2; sp++) {
                CP_ASYNC16(smem_u32(&sA[st][sp][lrow * 16 + lch]),
                           gA[sp] + (s + 2) * 16);
                CP_ASYNC16(smem_u32(&sB[st][sp][lrow * 16 + lch]),
                           gB[sp] + (s + 2) * 16);
            }
            CP_COMMIT();
        }
    }

    // epilogue: direct float2 stores
    #pragma unroll
    for (int mi = 0; mi < 4; mi++) {
        int r = m0 + wm + mi * 16 + (lane >> 2);
        #pragma unroll
        for (int ni = 0; ni < 4; ni++) {
            int c = n0 + wn + ni * 8 + (lane & 3) * 2;
            *(float2*)&C[(size_t)r * N + c] = make_float2(d[mi][ni][0], d[mi][ni][1]);
            *(float2*)&C[(size_t)(r + 8) * N + c] = make_float2(d[mi][ni][2], d[mi][ni][3]);
        }
    }
}

// ---------------- fused QK-LN + RoPE + transpose + V copy ----------------
__global__ void qk_rope_kernel(const float* __restrict__ qw,
                               const float* __restrict__ kw) {
    int n = blockIdx.x;
    int b = n >> 11;
    int l = n & 2047;
    const float* q = g_qkv + (size_t)n * D3;
    const float* k = q + D_;
    const float* v = q + 2 * D_;
    int t = threadIdx.x;

    float4 qv = *(const float4*)&q[t * 4];
    float4 kv = *(const float4*)&k[t * 4];
    float qs  = qv.x + qv.y + qv.z + qv.w;
    float qs2 = qv.x*qv.x + qv.y*qv.y + qv.z*qv.z + qv.w*qv.w;
    float ks  = kv.x + kv.y + kv.z + kv.w;
    float ks2 = kv.x*kv.x + kv.y*kv.y + kv.z*kv.z + kv.w*kv.w;
    #pragma unroll
    for (int o = 16; o >= 1; o >>= 1) {
        qs  += __shfl_xor_sync(0xffffffffu, qs,  o);
        qs2 += __shfl_xor_sync(0xffffffffu, qs2, o);
        ks  += __shfl_xor_sync(0xffffffffu, ks,  o);
        ks2 += __shfl_xor_sync(0xffffffffu, ks2, o);
    }
    __shared__ float red[4][8];
    __shared__ float stat[4];
    __shared__ float qn[D_], kn[D_];
    int lane = t & 31, wp = t >> 5;
    if (lane == 0) { red[0][wp]=qs; red[1][wp]=qs2; red[2][wp]=ks; red[3][wp]=ks2; }
    __syncthreads();
    if (t == 0) {
        float a=0,c=0,e=0,f=0;
        #pragma unroll
        for (int i=0;i<8;i++){a+=red[0][i];c+=red[1][i];e+=red[2][i];f+=red[3][i];}
        float qmu=a*(1.f/D_), qvr=c*(1.f/D_)-qmu*qmu;
        float kmu=e*(1.f/D_), kvr=f*(1.f/D_)-kmu*kmu;
        stat[0]=qmu; stat[1]=rsqrtf(qvr+EPS);
        stat[2]=kmu; stat[3]=rsqrtf(kvr+EPS);
    }
    __syncthreads();
    float qmu=stat[0], qrs=stat[1], kmu=stat[2], krs=stat[3];
    float4 qwv = *(const float4*)&qw[t*4];
    float4 kwv = *(const float4*)&kw[t*4];
    qn[t*4+0]=(qv.x-qmu)*qrs*qwv.x; qn[t*4+1]=(qv.y-qmu)*qrs*qwv.y;
    qn[t*4+2]=(qv.z-qmu)*qrs*qwv.z; qn[t*4+3]=(qv.w-qmu)*qrs*qwv.w;
    kn[t*4+0]=(kv.x-kmu)*krs*kwv.x; kn[t*4+1]=(kv.y-kmu)*krs*kwv.y;
    kn[t*4+2]=(kv.z-kmu)*krs*kwv.z; kn[t*4+3]=(kv.w-kmu)*krs*kwv.w;
    __syncthreads();

    int d0 = t * 4;
    int h  = d0 >> 6;
    int j0 = d0 & 63;
    float qo[4], ko[4];
    #pragma unroll
    for (int ii = 0; ii < 4; ii++) {
        int d = d0 + ii;
        int j = j0 + ii;
        int f = j & 31;
        float c = g_cos[l * 32 + f];
        float s = g_sin[l * 32 + f];
        if (j < 32) {
            qo[ii] = qn[d] * c - qn[d + 32] * s;
            ko[ii] = kn[d] * c - kn[d + 32] * s;
        } else {
            qo[ii] = qn[d] * c + qn[d - 32] * s;
            ko[ii] = kn[d] * c + kn[d - 32] * s;
        }
    }
    size_t oidx = ((((size_t)b * H_ + h) * L_) + l) * DH + j0;
    *(float4*)&g_qT[oidx] = make_float4(qo[0], qo[1], qo[2], qo[3]);
    *(float4*)&g_kT[oidx] = make_float4(ko[0], ko[1], ko[2], ko[3]);
    *(float4*)&g_vT[oidx] = *(const float4*)&v[d0];
}

// ---------------- flash attention (fp32, f32x2 mainloops) ----------------
#define PS_STRIDE 68
#define ATT_SMEM_FLOATS (64*64*3 + 64*PS_STRIDE + 6*64 + 128)
#define ATT_SMEM_BYTES  (ATT_SMEM_FLOATS * 4)

__global__ __launch_bounds__(256) void attn_kernel(const int* __restrict__ seq_id) {
    extern __shared__ float sm[];
    float* Qt  = sm;
    float* Kt  = Qt + 64 * 64;
    float* Vs  = Kt + 64 * 64;
    float* Ps  = Vs + 64 * 64;
    float* mi  = Ps + 64 * PS_STRIDE;
    float* li  = mi  + 64;
    float* al  = li  + 64;
    float* mn  = al  + 64;
    float* tmx = mn  + 64;
    float* tsm = tmx + 64;
    int*   sq  = (int*)(tsm + 64);
    int*   sk  = sq + 64;

    int tid = threadIdx.x;
    int tx = tid & 15, ty = tid >> 4;
    int qt = blockIdx.x, h = blockIdx.y, b = blockIdx.z;
    int row0 = qt * 64;
    const float* qb = g_qT + (((size_t)(b * H_ + h)) * L_ + row0) * DH;
    const float* kb0 = g_kT + ((size_t)(b * H_ + h)) * L_ * DH;
    const float* vb0 = g_vT + ((size_t)(b * H_ + h)) * L_ * DH;

    {
        int r = tid >> 2, d4 = (tid & 3) * 16;
        #pragma unroll
        for (int ii = 0; ii < 4; ii++) {
            int d = d4 + ii * 4;
            float4 q4 = *(const float4*)&qb[r * DH + d];
            Qt[(d+0)*64 + r] = q4.x; Qt[(d+1)*64 + r] = q4.y;
            Qt[(d+2)*64 + r] = q4.z; Qt[(d+3)*64 + r] = q4.w;
        }
    }
    if (tid < 64) {
        sq[tid] = seq_id[b * L_ + row0 + tid];
        mi[tid] = -1e30f;
        li[tid] = 0.0f;
    }
    ull acc2[4][2];
    #pragma unroll
    for (int i=0;i<4;i++) { acc2[i][0] = 0ULL; acc2[i][1] = 0ULL; }
    __syncthreads();

    for (int mt = 0; mt < L_ / 64; mt++) {
        int col0 = mt * 64;
        const float* kbt = kb0 + (size_t)col0 * DH;
        const float* vbt = vb0 + (size_t)col0 * DH;
        {
            int c = tid >> 2, d4 = (tid & 3) * 16;
            #pragma unroll
            for (int ii = 0; ii < 4; ii++) {
                int d = d4 + ii * 4;
                float4 k4 = *(const float4*)&kbt[c * DH + d];
                Kt[(d+0)*64 + c] = k4.x; Kt[(d+1)*64 + c] = k4.y;
                Kt[(d+2)*64 + c] = k4.z; Kt[(d+3)*64 + c] = k4.w;
                *(float4*)&Vs[c * 64 + d] = *(const float4*)&vbt[c * DH + d];
            }
        }
        if (tid < 64) sk[tid] = seq_id[b * L_ + col0 + tid];
        __syncthreads();

        ull s2[4][2];
        #pragma unroll
        for (int i=0;i<4;i++) { s2[i][0] = 0ULL; s2[i][1] = 0ULL; }
        #pragma unroll
        for (int d = 0; d < 64; d++) {
            float4 q4 = *(const float4*)&Qt[d * 64 + ty * 4];
            const ull* kp = (const ull*)&Kt[d * 64 + tx * 4];
            ull kb0p = kp[0], kb1p = kp[1];
            float qa[4] = {q4.x, q4.y, q4.z, q4.w};
            #pragma unroll
            for (int i=0;i<4;i++) {
                ull pq = pk2(qa[i], qa[i]);
                fma2(s2[i][0], pq, kb0p);
                fma2(s2[i][1], pq, kb1p);
            }
        }
        float s[4][4];
        #pragma unroll
        for (int i=0;i<4;i++) {
            float2 u0 = upk(s2[i][0]);
            float2 u1 = upk(s2[i][1]);
            s[i][0] = u0.x; s[i][1] = u0.y; s[i][2] = u1.x; s[i][3] = u1.y;
        }
        const float scale = 0.125f;
        int myq[4], myk[4];
        #pragma unroll
        for (int i=0;i<4;i++) myq[i] = sq[ty*4+i];
        #pragma unroll
        for (int j=0;j<4;j++) myk[j] = sk[tx*4+j];
        #pragma unroll
        for (int i=0;i<4;i++)
            #pragma unroll
            for (int j=0;j<4;j++)
                s[i][j] = (myq[i] == myk[j]) ? s[i][j] * scale : -2e30f;

        #pragma unroll
        for (int i=0;i<4;i++) {
            float m = fmaxf(fmaxf(s[i][0], s[i][1]), fmaxf(s[i][2], s[i][3]));
            #pragma unroll
            for (int o = 8; o >= 1; o >>= 1)
                m = fmaxf(m, __shfl_xor_sync(0xffffffffu, m, o));
            if (tx == 0) tmx[ty*4+i] = m;
        }
        __syncthreads();
        if (tid < 64) {
            float mo = mi[tid];
            float m2 = fmaxf(mo, tmx[tid]);
            al[tid] = __expf(mo - m2);
            mi[tid] = m2;
            mn[tid] = m2;
        }
        __syncthreads();

        #pragma unroll
        for (int i=0;i<4;i++) {
            float m2 = mn[ty*4+i];
            float p0 = __expf(s[i][0] - m2);
            float p1 = __expf(s[i][1] - m2);
            float p2 = __expf(s[i][2] - m2);
            float p3 = __expf(s[i][3] - m2);
            *(float4*)&Ps[(ty*4+i) * PS_STRIDE + tx*4] = make_float4(p0,p1,p2,p3);
            float rs = p0 + p1 + p2 + p3;
            #pragma unroll
            for (int o = 8; o >= 1; o >>= 1)
                rs += __shfl_xor_sync(0xffffffffu, rs, o);
            if (tx == 0) tsm[ty*4+i] = rs;
            float a = al[ty*4+i];
            ull aa = pk2(a, a);
            acc2[i][0] = mul2(acc2[i][0], aa);
            acc2[i][1] = mul2(acc2[i][1], aa);
        }
        __syncthreads();
        if (tid < 64) li[tid] = li[tid] * al[tid] + tsm[tid];

        #pragma unroll
        for (int c = 0; c < 64; c++) {
            const ull* vp = (const ull*)&Vs[c * 64 + tx * 4];
            ull vb0p = vp[0], vb1p = vp[1];
            #pragma unroll
            for (int i=0;i<4;i++) {
                float p = Ps[(ty*4+i) * PS_STRIDE + c];
                ull pp = pk2(p, p);
                fma2(acc2[i][0], pp, vb0p);
                fma2(acc2[i][1], pp, vb1p);
            }
        }
        __syncthreads();
    }

    // epilogue: ctx -> bf16 hi/lo for out-proj MMA GEMM
    #pragma unroll
    for (int i=0;i<4;i++) {
        float inv = 1.0f / li[ty*4+i];
        int r = row0 + ty*4 + i;
        size_t o = (((size_t)b * L_ + r) * H_ + h) * DH + tx * 4;
        float2 u0 = upk(acc2[i][0]);
        float2 u1 = upk(acc2[i][1]);
        float vv[4] = {u0.x*inv, u0.y*inv, u1.x*inv, u1.y*inv};
        union { __nv_bfloat16 hh[4]; uint2 u; } uh, ul;
        #pragma unroll
        for (int j=0;j<4;j++) {
            __nv_bfloat16 hb = __float2bfloat16(vv[j]);
            uh.hh[j] = hb;
            ul.hh[j] = __float2bfloat16(vv[j] - __bfloat162float(hb));
        }
        *(uint2*)&g_ch[o] = uh.u;
        *(uint2*)&g_cl[o] = ul.u;
    }
}

// ---------------- launch ----------------
extern "C" void kernel_launch(void* const* d_in, const int* in_sizes, int n_in,
                              void* d_out, int out_size) {
    const float* x      = (const float*)d_in[0];
    const int*   seq_id = (const int*)  d_in[1];
    const float* ln1_w  = (const float*)d_in[2];
    const float* ln1_b  = (const float*)d_in[3];
    const float* w_qkv  = (const float*)d_in[4];
    const float* q_ln_w = (const float*)d_in[5];
    const float* k_ln_w = (const float*)d_in[6];
    const float* out_w  = (const float*)d_in[7];
    float* out = (float*)d_out;

    void *phh, *phl, *pwqh, *pwql, *powh, *powl, *pch, *pcl, *pqkv;
    cudaGetSymbolAddress(&phh,  g_hh);
    cudaGetSymbolAddress(&phl,  g_hl);
    cudaGetSymbolAddress(&pwqh, g_wqh);
    cudaGetSymbolAddress(&pwql, g_wql);
    cudaGetSymbolAddress(&powh, g_owh);
    cudaGetSymbolAddress(&powl, g_owl);
    cudaGetSymbolAddress(&pch,  g_ch);
    cudaGetSymbolAddress(&pcl,  g_cl);
    cudaGetSymbolAddress(&pqkv, g_qkv);

    cudaFuncSetAttribute(attn_kernel, cudaFuncAttributeMaxDynamicSharedMemorySize,
                         ATT_SMEM_BYTES);

    rope_table_kernel<<<(L_ * 32 + 255) / 256, 256>>>();
    split_kernel<<<(D3 * D_) / 1024, 256>>>(w_qkv, (__nv_bfloat16*)pwqh,
                                            (__nv_bfloat16*)pwql);
    split_kernel<<<(D_ * D_) / 1024, 256>>>(out_w, (__nv_bfloat16*)powh,
                                            (__nv_bfloat16*)powl);
    ln1_kernel<<<NT, 256>>>(x, ln1_w, ln1_b);
    gemm_mma<<<dim3(D3 / 128, NT / 128), 256>>>(
        (const __nv_bfloat16*)phh, (const __nv_bfloat16*)phl,
        (const __nv_bfloat16*)pwqh, (const __nv_bfloat16*)pwql,
        (float*)pqkv, NT, D3, D_);
    qk_rope_kernel<<<NT, 256>>>(q_ln_w, k_ln_w);
    attn_kernel<<<dim3(L_ / 64, H_, B_), 256, ATT_SMEM_BYTES>>>(seq_id);
    gemm_mma<<<dim3(D_ / 128, NT / 128), 256>>>(
        (const __nv_bfloat16*)pch, (const __nv_bfloat16*)pcl,
        (const __nv_bfloat16*)powh, (const __nv_bfloat16*)powl,
        out, NT, D_, D_);
}

// round 6
// speedup vs baseline: 2.3617x; 1.7512x over previous
#include <cuda_runtime.h>
#include <cuda_bf16.h>
#include <cstdint>
#include <math.h>

// Problem constants
#define B_  2
#define L_  2048
#define NT  4096            // B*L tokens
#define D_  1024
#define H_  16
#define DH  64
#define D3  3072
#define EPS 1e-5f

// ---------------- scratch (device globals; no allocation) ----------------
__device__ __nv_bfloat16 g_hh[NT * D_];   // LN1 out hi
__device__ __nv_bfloat16 g_hl[NT * D_];   // LN1 out lo
__device__ __nv_bfloat16 g_wqh[D3 * D_];  // w_qkv hi
__device__ __nv_bfloat16 g_wql[D3 * D_];  // w_qkv lo
__device__ __nv_bfloat16 g_owh[D_ * D_];  // out_w hi
__device__ __nv_bfloat16 g_owl[D_ * D_];  // out_w lo
__device__ __nv_bfloat16 g_ch[NT * D_];   // ctx hi   [B,L,H,DH] == [NT,D]
__device__ __nv_bfloat16 g_cl[NT * D_];   // ctx lo
__device__ __nv_bfloat16 g_qh[NT * D_];   // q (scaled) hi  [BH,L,DH]
__device__ __nv_bfloat16 g_ql[NT * D_];
__device__ __nv_bfloat16 g_kh[NT * D_];   // k hi [BH,L,DH]
__device__ __nv_bfloat16 g_kl[NT * D_];
__device__ __nv_bfloat16 g_vth[NT * D_];  // v^T hi [BH,DH,L]
__device__ __nv_bfloat16 g_vtl[NT * D_];
__device__ float g_qkv[NT * D3];          // QKV gemm output [NT, 3D]
__device__ float g_cos[L_ * 32];
__device__ float g_sin[L_ * 32];

// ---------------- helpers ----------------
__device__ __forceinline__ uint32_t smem_u32(const void* p) {
    uint32_t a;
    asm("{ .reg .u64 t; cvta.to.shared.u64 t, %1; cvt.u32.u64 %0, t; }"
        : "=r"(a) : "l"(p));
    return a;
}
#define CP_ASYNC16(dst, src) \
    asm volatile("cp.async.cg.shared.global [%0], [%1], 16;" :: "r"(dst), "l"(src))
#define CP_COMMIT() asm volatile("cp.async.commit_group;" ::: "memory")
#define CP_WAIT0()  asm volatile("cp.async.wait_group 0;" ::: "memory")
#define CP_WAIT1()  asm volatile("cp.async.wait_group 1;" ::: "memory")

// mma.sync m16n8k16 bf16 -> fp32 (legacy HMMA path, valid on compute_103)
#define MMA16816(d, a, b) \
    asm volatile( \
        "mma.sync.aligned.m16n8k16.row.col.f32.bf16.bf16.f32 " \
        "{%0,%1,%2,%3}, {%4,%5,%6,%7}, {%8,%9}, {%0,%1,%2,%3};" \
        : "+f"((d)[0]), "+f"((d)[1]), "+f"((d)[2]), "+f"((d)[3]) \
        : "r"((a)[0]), "r"((a)[1]), "r"((a)[2]), "r"((a)[3]), \
          "r"((b)[0]), "r"((b)[1]))

// ---------------- RoPE table ----------------
__global__ void rope_table_kernel() {
    int idx = blockIdx.x * blockDim.x + threadIdx.x;
    if (idx >= L_ * 32) return;
    int l = idx >> 5;
    int j = idx & 31;
    float inv = powf(10000.0f, -(float)j / 32.0f);
    float ang = (float)l * inv;
    float s, c;
    sincosf(ang, &s, &c);
    g_cos[idx] = c;
    g_sin[idx] = s;
}

// ---------------- hi/lo bf16 split for weights ----------------
__global__ void split_kernel(const float* __restrict__ x,
                             __nv_bfloat16* __restrict__ hi,
                             __nv_bfloat16* __restrict__ lo) {
    int i = (blockIdx.x * 256 + threadIdx.x) * 4;
    float4 v = *(const float4*)&x[i];
    float vv[4] = {v.x, v.y, v.z, v.w};
    union { __nv_bfloat16 h[4]; uint2 u; } a, b;
    #pragma unroll
    for (int j = 0; j < 4; j++) {
        __nv_bfloat16 hb = __float2bfloat16(vv[j]);
        a.h[j] = hb;
        b.h[j] = __float2bfloat16(vv[j] - __bfloat162float(hb));
    }
    *(uint2*)&hi[i] = a.u;
    *(uint2*)&lo[i] = b.u;
}

// ---------------- LN1 -> bf16 hi/lo ----------------
__global__ void ln1_kernel(const float* __restrict__ x,
                           const float* __restrict__ w,
                           const float* __restrict__ b) {
    int n = blockIdx.x;
    const float* xr = x + (size_t)n * D_;
    int t = threadIdx.x;
    float4 v = *(const float4*)&xr[t * 4];
    float s  = v.x + v.y + v.z + v.w;
    float s2 = v.x*v.x + v.y*v.y + v.z*v.z + v.w*v.w;
    #pragma unroll
    for (int o = 16; o >= 1; o >>= 1) {
        s  += __shfl_xor_sync(0xffffffffu, s,  o);
        s2 += __shfl_xor_sync(0xffffffffu, s2, o);
    }
    __shared__ float red[2][8];
    int lane = t & 31, wp = t >> 5;
    if (lane == 0) { red[0][wp] = s; red[1][wp] = s2; }
    __syncthreads();
    __shared__ float stat[2];
    if (t == 0) {
        float a = 0.f, c = 0.f;
        #pragma unroll
        for (int i = 0; i < 8; i++) { a += red[0][i]; c += red[1][i]; }
        float mu  = a * (1.0f / D_);
        float var = c * (1.0f / D_) - mu * mu;
        stat[0] = mu;
        stat[1] = rsqrtf(var + EPS);
    }
    __syncthreads();
    float mu = stat[0], rs = stat[1];
    float4 wv = *(const float4*)&w[t * 4];
    float4 bv = *(const float4*)&b[t * 4];
    float oo[4];
    oo[0] = (v.x - mu) * rs * wv.x + bv.x;
    oo[1] = (v.y - mu) * rs * wv.y + bv.y;
    oo[2] = (v.z - mu) * rs * wv.z + bv.z;
    oo[3] = (v.w - mu) * rs * wv.w + bv.w;
    union { __nv_bfloat16 h[4]; uint2 u; } a, bb;
    #pragma unroll
    for (int j = 0; j < 4; j++) {
        __nv_bfloat16 hb = __float2bfloat16(oo[j]);
        a.h[j]  = hb;
        bb.h[j] = __float2bfloat16(oo[j] - __bfloat162float(hb));
    }
    size_t oidx = (size_t)n * D_ + t * 4;
    *(uint2*)&g_hh[oidx] = a.u;
    *(uint2*)&g_hl[oidx] = bb.u;
}

// ============ warp-MMA bf16 split-3 GEMM (unchanged from R4) ============
__global__ __launch_bounds__(256) void gemm_mma(
    const __nv_bfloat16* __restrict__ Ah, const __nv_bfloat16* __restrict__ Al,
    const __nv_bfloat16* __restrict__ Bh, const __nv_bfloat16* __restrict__ Bl,
    float* __restrict__ C, int M, int N, int K)
{
    __shared__ __nv_bfloat16 sA[2][2][128 * 16];
    __shared__ __nv_bfloat16 sB[2][2][128 * 16];

    int tid = threadIdx.x;
    int warp = tid >> 5, lane = tid & 31;
    int m0 = blockIdx.y * 128, n0 = blockIdx.x * 128;
    int wm = (warp & 1) * 64, wn = (warp >> 1) * 32;

    int lrow = tid >> 1;
    int lch  = (tid & 1) * 8;

    const __nv_bfloat16* gA[2] = {Ah + (size_t)(m0 + lrow) * K + lch,
                                  Al + (size_t)(m0 + lrow) * K + lch};
    const __nv_bfloat16* gB[2] = {Bh + (size_t)(n0 + lrow) * K + lch,
                                  Bl + (size_t)(n0 + lrow) * K + lch};

    float d[4][4][4];
    #pragma unroll
    for (int mi = 0; mi < 4; mi++)
        #pragma unroll
        for (int ni = 0; ni < 4; ni++)
            #pragma unroll
            for (int r = 0; r < 4; r++) d[mi][ni][r] = 0.f;

    const int nstep = K >> 4;

    #pragma unroll
    for (int s = 0; s < 2; s++) {
        int st = s & 1;
        #pragma unroll
        for (int sp = 0; sp < 2; sp++) {
            CP_ASYNC16(smem_u32(&sA[st][sp][lrow * 16 + lch]), gA[sp] + s * 16);
            CP_ASYNC16(smem_u32(&sB[st][sp][lrow * 16 + lch]), gB[sp] + s * 16);
        }
        CP_COMMIT();
    }

    int ar = wm + (lane >> 2);
    int ac = (lane & 3) * 2;
    int br = wn + (lane >> 2);
    int bc = (lane & 3) * 2;

    for (int s = 0; s < nstep; s++) {
        int st = s & 1;
        if (s == nstep - 1) { CP_WAIT0(); } else { CP_WAIT1(); }
        __syncthreads();

        const __nv_bfloat16* pAh = &sA[st][0][0];
        const __nv_bfloat16* pAl = &sA[st][1][0];
        const __nv_bfloat16* pBh = &sB[st][0][0];
        const __nv_bfloat16* pBl = &sB[st][1][0];

        uint32_t ah[4][4], al[4][4], bh[4][2], bl[4][2];
        #pragma unroll
        for (int mi = 0; mi < 4; mi++) {
            int r0 = (ar + mi * 16) * 16 + ac;
            int r1 = r0 + 8 * 16;
            ah[mi][0] = *(const uint32_t*)(pAh + r0);
            ah[mi][1] = *(const uint32_t*)(pAh + r1);
            ah[mi][2] = *(const uint32_t*)(pAh + r0 + 8);
            ah[mi][3] = *(const uint32_t*)(pAh + r1 + 8);
            al[mi][0] = *(const uint32_t*)(pAl + r0);
            al[mi][1] = *(const uint32_t*)(pAl + r1);
            al[mi][2] = *(const uint32_t*)(pAl + r0 + 8);
            al[mi][3] = *(const uint32_t*)(pAl + r1 + 8);
        }
        #pragma unroll
        for (int ni = 0; ni < 4; ni++) {
            int c0 = (br + ni * 8) * 16 + bc;
            bh[ni][0] = *(const uint32_t*)(pBh + c0);
            bh[ni][1] = *(const uint32_t*)(pBh + c0 + 8);
            bl[ni][0] = *(const uint32_t*)(pBl + c0);
            bl[ni][1] = *(const uint32_t*)(pBl + c0 + 8);
        }

        #pragma unroll
        for (int mi = 0; mi < 4; mi++)
            #pragma unroll
            for (int ni = 0; ni < 4; ni++) {
                MMA16816(d[mi][ni], ah[mi], bh[ni]);
                MMA16816(d[mi][ni], ah[mi], bl[ni]);
                MMA16816(d[mi][ni], al[mi], bh[ni]);
            }

        __syncthreads();
        if (s + 2 < nstep) {
            #pragma unroll
            for (int sp = 0; sp < 2; sp++) {
                CP_ASYNC16(smem_u32(&sA[st][sp][lrow * 16 + lch]),
                           gA[sp] + (s + 2) * 16);
                CP_ASYNC16(smem_u32(&sB[st][sp][lrow * 16 + lch]),
                           gB[sp] + (s + 2) * 16);
            }
            CP_COMMIT();
        }
    }

    #pragma unroll
    for (int mi = 0; mi < 4; mi++) {
        int r = m0 + wm + mi * 16 + (lane >> 2);
        #pragma unroll
        for (int ni = 0; ni < 4; ni++) {
            int c = n0 + wn + ni * 8 + (lane & 3) * 2;
            *(float2*)&C[(size_t)r * N + c] = make_float2(d[mi][ni][0], d[mi][ni][1]);
            *(float2*)&C[(size_t)(r + 8) * N + c] = make_float2(d[mi][ni][2], d[mi][ni][3]);
        }
    }
}

// ---------------- fused QK-LN + RoPE -> bf16 hi/lo [BH,L,DH] ----------------
__global__ void qk_rope_kernel(const float* __restrict__ qw,
                               const float* __restrict__ kw) {
    int n = blockIdx.x;
    int b = n >> 11;
    int l = n & 2047;
    const float* q = g_qkv + (size_t)n * D3;
    const float* k = q + D_;
    int t = threadIdx.x;

    float4 qv = *(const float4*)&q[t * 4];
    float4 kv = *(const float4*)&k[t * 4];
    float qs  = qv.x + qv.y + qv.z + qv.w;
    float qs2 = qv.x*qv.x + qv.y*qv.y + qv.z*qv.z + qv.w*qv.w;
    float ks  = kv.x + kv.y + kv.z + kv.w;
    float ks2 = kv.x*kv.x + kv.y*kv.y + kv.z*kv.z + kv.w*kv.w;
    #pragma unroll
    for (int o = 16; o >= 1; o >>= 1) {
        qs  += __shfl_xor_sync(0xffffffffu, qs,  o);
        qs2 += __shfl_xor_sync(0xffffffffu, qs2, o);
        ks  += __shfl_xor_sync(0xffffffffu, ks,  o);
        ks2 += __shfl_xor_sync(0xffffffffu, ks2, o);
    }
    __shared__ float red[4][8];
    __shared__ float stat[4];
    __shared__ float qn[D_], kn[D_];
    int lane = t & 31, wp = t >> 5;
    if (lane == 0) { red[0][wp]=qs; red[1][wp]=qs2; red[2][wp]=ks; red[3][wp]=ks2; }
    __syncthreads();
    if (t == 0) {
        float a=0,c=0,e=0,f=0;
        #pragma unroll
        for (int i=0;i<8;i++){a+=red[0][i];c+=red[1][i];e+=red[2][i];f+=red[3][i];}
        float qmu=a*(1.f/D_), qvr=c*(1.f/D_)-qmu*qmu;
        float kmu=e*(1.f/D_), kvr=f*(1.f/D_)-kmu*kmu;
        stat[0]=qmu; stat[1]=rsqrtf(qvr+EPS);
        stat[2]=kmu; stat[3]=rsqrtf(kvr+EPS);
    }
    __syncthreads();
    float qmu=stat[0], qrs=stat[1], kmu=stat[2], krs=stat[3];
    float4 qwv = *(const float4*)&qw[t*4];
    float4 kwv = *(const float4*)&kw[t*4];
    qn[t*4+0]=(qv.x-qmu)*qrs*qwv.x; qn[t*4+1]=(qv.y-qmu)*qrs*qwv.y;
    qn[t*4+2]=(qv.z-qmu)*qrs*qwv.z; qn[t*4+3]=(qv.w-qmu)*qrs*qwv.w;
    kn[t*4+0]=(kv.x-kmu)*krs*kwv.x; kn[t*4+1]=(kv.y-kmu)*krs*kwv.y;
    kn[t*4+2]=(kv.z-kmu)*krs*kwv.z; kn[t*4+3]=(kv.w-kmu)*krs*kwv.w;
    __syncthreads();

    int d0 = t * 4;
    int hh = d0 >> 6;
    int j0 = d0 & 63;
    float qo[4], ko[4];
    #pragma unroll
    for (int ii = 0; ii < 4; ii++) {
        int d = d0 + ii;
        int j = j0 + ii;
        int f = j & 31;
        float c = g_cos[l * 32 + f];
        float s = g_sin[l * 32 + f];
        if (j < 32) {
            qo[ii] = qn[d] * c - qn[d + 32] * s;
            ko[ii] = kn[d] * c - kn[d + 32] * s;
        } else {
            qo[ii] = qn[d] * c + qn[d - 32] * s;
            ko[ii] = kn[d] * c + kn[d - 32] * s;
        }
        qo[ii] *= 0.125f;   // fold softmax scale into q
    }
    size_t oidx = (((size_t)(b * H_ + hh)) * L_ + l) * DH + j0;
    union { __nv_bfloat16 h[4]; uint2 u; } uqh, uql, ukh, ukl;
    #pragma unroll
    for (int ii = 0; ii < 4; ii++) {
        __nv_bfloat16 hb = __float2bfloat16(qo[ii]);
        uqh.h[ii] = hb;
        uql.h[ii] = __float2bfloat16(qo[ii] - __bfloat162float(hb));
        __nv_bfloat16 kb = __float2bfloat16(ko[ii]);
        ukh.h[ii] = kb;
        ukl.h[ii] = __float2bfloat16(ko[ii] - __bfloat162float(kb));
    }
    *(uint2*)&g_qh[oidx] = uqh.u;
    *(uint2*)&g_ql[oidx] = uql.u;
    *(uint2*)&g_kh[oidx] = ukh.u;
    *(uint2*)&g_kl[oidx] = ukl.u;
}

// ---------------- V transpose: g_qkv v-part -> [BH,DH,L] bf16 hi/lo ----------------
__global__ void vt_kernel() {
    __shared__ float tile[64][33];
    int bh = blockIdx.y;
    int b = bh >> 4, h = bh & 15;
    int l0 = blockIdx.x * 32;
    int tx = threadIdx.x & 31, ty = threadIdx.x >> 5;   // 256 threads

    #pragma unroll
    for (int i = 0; i < 4; i++) {
        int l = l0 + ty + i * 8;
        const float* row = g_qkv + (size_t)(b * L_ + l) * D3 + 2 * D_ + h * DH;
        tile[tx][ty + i * 8]      = row[tx];
        tile[tx + 32][ty + i * 8] = row[tx + 32];
    }
    __syncthreads();
    #pragma unroll
    for (int i = 0; i < 8; i++) {
        int d = ty + i * 8;
        float v = tile[d][tx];
        __nv_bfloat16 hb = __float2bfloat16(v);
        __nv_bfloat16 lb = __float2bfloat16(v - __bfloat162float(hb));
        size_t o = (size_t)(bh * DH + d) * L_ + l0 + tx;
        g_vth[o] = hb;
        g_vtl[o] = lb;
    }
}

// ---------------- flash attention on mma.sync (bf16 split-3) ----------------
#define KPAD 72
#define AT_SM_QH 0
#define AT_SM_QL 9216
#define AT_SM_KV 18432
#define AT_SM_TILE 9216
#define AT_SM_BUF 36864
#define AT_SM_SK (18432 + 2 * 36864)
#define ATT2_SMEM (AT_SM_SK + 512)

__global__ __launch_bounds__(128) void attn_mma(const int* __restrict__ seq_id) {
    extern __shared__ char sm[];
    const uint32_t sbase = smem_u32(sm);
    int tid = threadIdx.x, lane = tid & 31, w = tid >> 5;
    int qt = blockIdx.x, h = blockIdx.y, b = blockIdx.z;
    int bh = b * H_ + h;
    int row0 = qt * 64;

    const __nv_bfloat16* gQh = g_qh + ((size_t)bh * L_ + row0) * DH;
    const __nv_bfloat16* gQl = g_ql + ((size_t)bh * L_ + row0) * DH;
    const __nv_bfloat16* gKh = g_kh + (size_t)bh * L_ * DH;
    const __nv_bfloat16* gKl = g_kl + (size_t)bh * L_ * DH;
    const __nv_bfloat16* gVh = g_vth + (size_t)bh * DH * L_;
    const __nv_bfloat16* gVl = g_vtl + (size_t)bh * DH * L_;

    int lrow = tid >> 1;          // 0..63
    int cb0  = (tid & 1) * 4;     // chunk base (16B chunks)

    // ---- prologue: Q tiles ----
    #pragma unroll
    for (int c = 0; c < 4; c++) {
        int ch = cb0 + c;
        uint32_t so = (uint32_t)(lrow * KPAD + ch * 8) * 2;
        CP_ASYNC16(sbase + AT_SM_QH + so, gQh + lrow * DH + ch * 8);
        CP_ASYNC16(sbase + AT_SM_QL + so, gQl + lrow * DH + ch * 8);
    }
    CP_COMMIT();
    // ---- K/V tile 0 ----
    {
        uint32_t dst = sbase + AT_SM_KV;
        #pragma unroll
        for (int c = 0; c < 4; c++) {
            int ch = cb0 + c;
            uint32_t so = (uint32_t)(lrow * KPAD + ch * 8) * 2;
            CP_ASYNC16(dst + so,                  gKh + (size_t)lrow * DH + ch * 8);
            CP_ASYNC16(dst + AT_SM_TILE + so,     gKl + (size_t)lrow * DH + ch * 8);
            CP_ASYNC16(dst + 2 * AT_SM_TILE + so, gVh + (size_t)lrow * L_ + ch * 8);
            CP_ASYNC16(dst + 3 * AT_SM_TILE + so, gVl + (size_t)lrow * L_ + ch * 8);
        }
    }
    CP_COMMIT();
    if (tid < 64) ((int*)(sm + AT_SM_SK))[tid] = seq_id[b * L_ + tid];
    int sq0 = seq_id[b * L_ + row0 + w * 16 + (lane >> 2)];
    int sq1 = seq_id[b * L_ + row0 + w * 16 + (lane >> 2) + 8];

    CP_WAIT1();
    __syncthreads();

    // ---- extract Q fragments (held for whole kernel) ----
    uint32_t qfh[4][4], qfl[4][4];
    {
        const __nv_bfloat16* sQh = (const __nv_bfloat16*)(sm + AT_SM_QH);
        const __nv_bfloat16* sQl = (const __nv_bfloat16*)(sm + AT_SM_QL);
        #pragma unroll
        for (int s = 0; s < 4; s++) {
            int base = (w * 16 + (lane >> 2)) * KPAD + s * 16 + (lane & 3) * 2;
            qfh[s][0] = *(const uint32_t*)(sQh + base);
            qfh[s][1] = *(const uint32_t*)(sQh + base + 8 * KPAD);
            qfh[s][2] = *(const uint32_t*)(sQh + base + 8);
            qfh[s][3] = *(const uint32_t*)(sQh + base + 8 * KPAD + 8);
            qfl[s][0] = *(const uint32_t*)(sQl + base);
            qfl[s][1] = *(const uint32_t*)(sQl + base + 8 * KPAD);
            qfl[s][2] = *(const uint32_t*)(sQl + base + 8);
            qfl[s][3] = *(const uint32_t*)(sQl + base + 8 * KPAD + 8);
        }
    }

    float m0 = -1e30f, m1 = -1e30f, l0 = 0.f, l1 = 0.f;
    float pv[8][4];
    #pragma unroll
    for (int j = 0; j < 8; j++)
        #pragma unroll
        for (int r = 0; r < 4; r++) pv[j][r] = 0.f;

    for (int it = 0; it < L_ / 64; it++) {
        int buf = it & 1;
        CP_WAIT0();
        __syncthreads();

        // prefetch next tile into other buffer
        if (it + 1 < L_ / 64) {
            int col0n = (it + 1) * 64;
            uint32_t dst = sbase + AT_SM_KV + (buf ^ 1) * AT_SM_BUF;
            #pragma unroll
            for (int c = 0; c < 4; c++) {
                int ch = cb0 + c;
                uint32_t so = (uint32_t)(lrow * KPAD + ch * 8) * 2;
                CP_ASYNC16(dst + so,                  gKh + (size_t)(col0n + lrow) * DH + ch * 8);
                CP_ASYNC16(dst + AT_SM_TILE + so,     gKl + (size_t)(col0n + lrow) * DH + ch * 8);
                CP_ASYNC16(dst + 2 * AT_SM_TILE + so, gVh + (size_t)lrow * L_ + col0n + ch * 8);
                CP_ASYNC16(dst + 3 * AT_SM_TILE + so, gVl + (size_t)lrow * L_ + col0n + ch * 8);
            }
            if (tid < 64)
                ((int*)(sm + AT_SM_SK))[(buf ^ 1) * 64 + tid] =
                    seq_id[b * L_ + col0n + tid];
        }
        CP_COMMIT();

        const __nv_bfloat16* sKh = (const __nv_bfloat16*)(sm + AT_SM_KV + buf * AT_SM_BUF);
        const __nv_bfloat16* sKl = sKh + 4608;
        const __nv_bfloat16* sVh = sKh + 9216;
        const __nv_bfloat16* sVl = sKh + 13824;
        const int* skp = (const int*)(sm + AT_SM_SK) + buf * 64;

        // ---- S = Q K^T (split-3) ----
        float sf[8][4];
        #pragma unroll
        for (int j = 0; j < 8; j++)
            #pragma unroll
            for (int r = 0; r < 4; r++) sf[j][r] = 0.f;
        #pragma unroll
        for (int s = 0; s < 4; s++) {
            #pragma unroll
            for (int j = 0; j < 8; j++) {
                int off = (j * 8 + (lane >> 2)) * KPAD + s * 16 + (lane & 3) * 2;
                uint32_t bhf[2] = {*(const uint32_t*)(sKh + off),
                                   *(const uint32_t*)(sKh + off + 8)};
                uint32_t blf[2] = {*(const uint32_t*)(sKl + off),
                                   *(const uint32_t*)(sKl + off + 8)};
                MMA16816(sf[j], qfh[s], bhf);
                MMA16816(sf[j], qfh[s], blf);
                MMA16816(sf[j], qfl[s], bhf);
            }
        }

        // ---- mask + online softmax (c-frag layout) ----
        int colb = (lane & 3) * 2;
        float nm0 = m0, nm1 = m1;
        #pragma unroll
        for (int j = 0; j < 8; j++) {
            int k0 = skp[8 * j + colb], k1 = skp[8 * j + colb + 1];
            sf[j][0] = (k0 == sq0) ? sf[j][0] : -2e30f;
            sf[j][1] = (k1 == sq0) ? sf[j][1] : -2e30f;
            sf[j][2] = (k0 == sq1) ? sf[j][2] : -2e30f;
            sf[j][3] = (k1 == sq1) ? sf[j][3] : -2e30f;
            nm0 = fmaxf(nm0, fmaxf(sf[j][0], sf[j][1]));
            nm1 = fmaxf(nm1, fmaxf(sf[j][2], sf[j][3]));
        }
        nm0 = fmaxf(nm0, __shfl_xor_sync(0xffffffffu, nm0, 1));
        nm0 = fmaxf(nm0, __shfl_xor_sync(0xffffffffu, nm0, 2));
        nm1 = fmaxf(nm1, __shfl_xor_sync(0xffffffffu, nm1, 1));
        nm1 = fmaxf(nm1, __shfl_xor_sync(0xffffffffu, nm1, 2));
        float a0 = __expf(m0 - nm0), a1 = __expf(m1 - nm1);
        m0 = nm0; m1 = nm1;

        float s0 = 0.f, s1 = 0.f;
        uint32_t ph[4][4], pl[4][4];
        #pragma unroll
        for (int j = 0; j < 8; j++) {
            float p0 = __expf(sf[j][0] - m0), p1 = __expf(sf[j][1] - m0);
            float p2 = __expf(sf[j][2] - m1), p3 = __expf(sf[j][3] - m1);
            s0 += p0 + p1; s1 += p2 + p3;
            __nv_bfloat162 h01 = __float22bfloat162_rn(make_float2(p0, p1));
            float2 f01 = __bfloat1622float2(h01);
            __nv_bfloat162 l01 = __float22bfloat162_rn(make_float2(p0 - f01.x, p1 - f01.y));
            __nv_bfloat162 h23 = __float22bfloat162_rn(make_float2(p2, p3));
            float2 f23 = __bfloat1622float2(h23);
            __nv_bfloat162 l23 = __float22bfloat162_rn(make_float2(p2 - f23.x, p3 - f23.y));
            int s_ = j >> 1;
            int o  = (j & 1) * 2;
            ph[s_][o]     = *(uint32_t*)&h01;
            ph[s_][o + 1] = *(uint32_t*)&h23;
            pl[s_][o]     = *(uint32_t*)&l01;
            pl[s_][o + 1] = *(uint32_t*)&l23;
        }
        s0 += __shfl_xor_sync(0xffffffffu, s0, 1);
        s0 += __shfl_xor_sync(0xffffffffu, s0, 2);
        s1 += __shfl_xor_sync(0xffffffffu, s1, 1);
        s1 += __shfl_xor_sync(0xffffffffu, s1, 2);
        l0 = l0 * a0 + s0;
        l1 = l1 * a1 + s1;
        #pragma unroll
        for (int j = 0; j < 8; j++) {
            pv[j][0] *= a0; pv[j][1] *= a0; pv[j][2] *= a1; pv[j][3] *= a1;
        }

        // ---- PV (split-3), B = Vt[dh][c] ----
        #pragma unroll
        for (int s = 0; s < 4; s++) {
            #pragma unroll
            for (int j = 0; j < 8; j++) {
                int off = (j * 8 + (lane >> 2)) * KPAD + s * 16 + (lane & 3) * 2;
                uint32_t bhf[2] = {*(const uint32_t*)(sVh + off),
                                   *(const uint32_t*)(sVh + off + 8)};
                uint32_t blf[2] = {*(const uint32_t*)(sVl + off),
                                   *(const uint32_t*)(sVl + off + 8)};
                MMA16816(pv[j], ph[s], bhf);
                MMA16816(pv[j], ph[s], blf);
                MMA16816(pv[j], pl[s], bhf);
            }
        }
    }

    // ---- epilogue: ctx / l -> bf16 hi/lo [B,L,H,DH] ----
    float inv0 = 1.0f / l0, inv1 = 1.0f / l1;
    int r0g = row0 + w * 16 + (lane >> 2);
    #pragma unroll
    for (int j = 0; j < 8; j++) {
        int c = 8 * j + (lane & 3) * 2;
        size_t o0 = (((size_t)b * L_ + r0g) * H_ + h) * DH + c;
        size_t o1 = (((size_t)b * L_ + r0g + 8) * H_ + h) * DH + c;
        float x0 = pv[j][0] * inv0, x1 = pv[j][1] * inv0;
        float y0 = pv[j][2] * inv1, y1 = pv[j][3] * inv1;
        __nv_bfloat162 hx = __float22bfloat162_rn(make_float2(x0, x1));
        float2 fx = __bfloat1622float2(hx);
        __nv_bfloat162 lx = __float22bfloat162_rn(make_float2(x0 - fx.x, x1 - fx.y));
        __nv_bfloat162 hy = __float22bfloat162_rn(make_float2(y0, y1));
        float2 fy = __bfloat1622float2(hy);
        __nv_bfloat162 ly = __float22bfloat162_rn(make_float2(y0 - fy.x, y1 - fy.y));
        *(uint32_t*)&g_ch[o0] = *(uint32_t*)&hx;
        *(uint32_t*)&g_cl[o0] = *(uint32_t*)&lx;
        *(uint32_t*)&g_ch[o1] = *(uint32_t*)&hy;
        *(uint32_t*)&g_cl[o1] = *(uint32_t*)&ly;
    }
}

// ---------------- launch ----------------
extern "C" void kernel_launch(void* const* d_in, const int* in_sizes, int n_in,
                              void* d_out, int out_size) {
    const float* x      = (const float*)d_in[0];
    const int*   seq_id = (const int*)  d_in[1];
    const float* ln1_w  = (const float*)d_in[2];
    const float* ln1_b  = (const float*)d_in[3];
    const float* w_qkv  = (const float*)d_in[4];
    const float* q_ln_w = (const float*)d_in[5];
    const float* k_ln_w = (const float*)d_in[6];
    const float* out_w  = (const float*)d_in[7];
    float* out = (float*)d_out;

    void *phh, *phl, *pwqh, *pwql, *powh, *powl, *pch, *pcl, *pqkv;
    cudaGetSymbolAddress(&phh,  g_hh);
    cudaGetSymbolAddress(&phl,  g_hl);
    cudaGetSymbolAddress(&pwqh, g_wqh);
    cudaGetSymbolAddress(&pwql, g_wql);
    cudaGetSymbolAddress(&powh, g_owh);
    cudaGetSymbolAddress(&powl, g_owl);
    cudaGetSymbolAddress(&pch,  g_ch);
    cudaGetSymbolAddress(&pcl,  g_cl);
    cudaGetSymbolAddress(&pqkv, g_qkv);

    cudaFuncSetAttribute(attn_mma, cudaFuncAttributeMaxDynamicSharedMemorySize,
                         ATT2_SMEM);

    rope_table_kernel<<<(L_ * 32 + 255) / 256, 256>>>();
    split_kernel<<<(D3 * D_) / 1024, 256>>>(w_qkv, (__nv_bfloat16*)pwqh,
                                            (__nv_bfloat16*)pwql);
    split_kernel<<<(D_ * D_) / 1024, 256>>>(out_w, (__nv_bfloat16*)powh,
                                            (__nv_bfloat16*)powl);
    ln1_kernel<<<NT, 256>>>(x, ln1_w, ln1_b);
    gemm_mma<<<dim3(D3 / 128, NT / 128), 256>>>(
        (const __nv_bfloat16*)phh, (const __nv_bfloat16*)phl,
        (const __nv_bfloat16*)pwqh, (const __nv_bfloat16*)pwql,
        (float*)pqkv, NT, D3, D_);
    qk_rope_kernel<<<NT, 256>>>(q_ln_w, k_ln_w);
    vt_kernel<<<dim3(L_ / 32, B_ * H_), 256>>>();
    attn_mma<<<dim3(L_ / 64, H_, B_), 128, ATT2_SMEM>>>(seq_id);
    gemm_mma<<<dim3(D_ / 128, NT / 128), 256>>>(
        (const __nv_bfloat16*)pch, (const __nv_bfloat16*)pcl,
        (const __nv_bfloat16*)powh, (const __nv_bfloat16*)powl,
        out, NT, D_, D_);
}